// round 14
// baseline (speedup 1.0000x reference)
#include <cuda_runtime.h>
#include <cuda_bf16.h>
#include <math.h>
#include <stdint.h>

#define NTOK   65586
#define MCLUS  50
#define NPATH  65536
#define DIM    256
#define SCALE  0.0625f

typedef __nv_bfloat16 bf16;

// ---------------- fp32 scratch ----------------------------------------------
__device__ float g_osc[MCLUS * DIM];
__device__ float g_occ[MCLUS * DIM];
__device__ float g_klsum[DIM];
__device__ float g_kv[DIM * DIM];
__device__ float g_zfac[NPATH];
__device__ float g_spin[(size_t)NPATH * DIM];
__device__ float g_Scap[(size_t)NPATH * 64];
__device__ float g_Scac[(size_t)NPATH * 64];
__device__ float g_pmax[64 * 64];
__device__ float g_cmax[64];
__device__ float g_clsum[64];
__device__ float g_Acp[NPATH];
__device__ float g_Asp[NPATH];
__device__ float g_Acc[MCLUS];
__device__ float g_Asc[MCLUS];
__device__ float g_fpart[2 * 256];   // partial maxima for big fmax
__device__ float g_fmax[4];
__device__ float g_fl[4];
__device__ float g_fh[4 * DIM];
__device__ float g_fw[64];
__device__ float g_ft[DIM];
__device__ float g_bfa2[DIM];
__device__ float g_bfb2[DIM];

// ---------------- bf16 hi/lo planes -----------------------------------------
__device__ __align__(16) bf16 qkvH[(size_t)NTOK * 768], qkvL[(size_t)NTOK * 768];
__device__ __align__(16) bf16 xH[(size_t)NTOK * 256],  xL[(size_t)NTOK * 256];
__device__ __align__(16) bf16 WqkvT_H[768 * 256], WqkvT_L[768 * 256];
__device__ __align__(16) bf16 vcabT_H[512 * 64], vcabT_L[512 * 64];
__device__ __align__(16) bf16 WfabT_H[(size_t)512 * 256], WfabT_L[(size_t)512 * 256];
__device__ __align__(16) bf16 kvT_H[256 * 256], kvT_L[256 * 256];
__device__ __align__(16) bf16 qlH[(size_t)NPATH * 256], qlL[(size_t)NPATH * 256];
__device__ __align__(16) bf16 klH[(size_t)NPATH * 256], klL[(size_t)NPATH * 256];
__device__ __align__(16) bf16 PH[(size_t)NPATH * 64],  PL[(size_t)NPATH * 64];
__device__ __align__(16) bf16 EH[(size_t)NPATH * 64],  EL[(size_t)NPATH * 64];
__device__ __align__(16) bf16 spinH[(size_t)NPATH * 256], spinL[(size_t)NPATH * 256];

__device__ __forceinline__ void splitbf(float v, bf16& h, bf16& l) {
    h = __float2bfloat16(v);
    l = __float2bfloat16(v - __bfloat162float(h));
}
__device__ __forceinline__ float recbf(const bf16* H, const bf16* L, size_t i) {
    return __bfloat162float(H[i]) + __bfloat162float(L[i]);
}

__global__ void init_kernel() {
    int t = blockIdx.x * 256 + threadIdx.x;
    int nthr = gridDim.x * 256;
    for (int i = t; i < NPATH; i += nthr) { g_Acp[i] = 0.f; g_Asp[i] = 0.f; }
    if (blockIdx.x == 0) {
        int c = threadIdx.x;
        for (int i = c; i < DIM * DIM; i += 256) g_kv[i] = 0.f;
        for (int i = c; i < MCLUS * DIM; i += 256) g_occ[i] = 0.f;
        if (c < DIM) { g_klsum[c] = 0.f; g_ft[c] = 0.f; }
        if (c < 64) { g_clsum[c] = 0.f; g_fw[c] = 0.f; }
        if (c < 4) g_fl[c] = 0.f;
        for (int i = c; i < 4 * DIM; i += 256) g_fh[i] = 0.f;
    }
}

__global__ void cvt_planar(const float* __restrict__ src, bf16* __restrict__ h,
                           bf16* __restrict__ l, int n) {
    int i = (blockIdx.x * 256 + threadIdx.x) * 4;
    if (i >= n) return;
    float4 v = *(const float4*)(src + i);
    bf16 a, b;
    splitbf(v.x, a, b); h[i+0]=a; l[i+0]=b;
    splitbf(v.y, a, b); h[i+1]=a; l[i+1]=b;
    splitbf(v.z, a, b); h[i+2]=a; l[i+2]=b;
    splitbf(v.w, a, b); h[i+3]=a; l[i+3]=b;
}

__global__ void transpose_cvt(const float* __restrict__ src, int ldsrc,
                              int R, int C, int Rpad,
                              bf16* __restrict__ dH, bf16* __restrict__ dL,
                              int rowMul, int rowOff) {
    __shared__ float t[32][33];
    int r0 = blockIdx.x * 32, c0 = blockIdx.y * 32;
    int tx = threadIdx.x, ty = threadIdx.y;
    for (int i = ty; i < 32; i += 8) {
        int r = r0 + i, c = c0 + tx;
        t[i][tx] = (r < R && c < C) ? src[(size_t)r * ldsrc + c] : 0.f;
    }
    __syncthreads();
    for (int i = ty; i < 32; i += 8) {
        int c = c0 + i, r = r0 + tx;
        if (c < C && r < Rpad) {
            bf16 h, l; splitbf(t[tx][i], h, l);
            size_t o = (size_t)(c * rowMul + rowOff) * Rpad + r;
            dH[o] = h; dL[o] = l;
        }
    }
}

// WfabT[2f+s][c] = sum_d Wf[c][d] * W{a,b}[d][f]
__global__ void make_wfab(const float* __restrict__ Wf,
                          const float* __restrict__ Wa, const float* __restrict__ Wb) {
    __shared__ float wrow[256];
    int c = blockIdx.x, f = threadIdx.x;
    wrow[f] = Wf[c * 256 + f];
    __syncthreads();
    float sa0 = 0.f, sa1 = 0.f, sb0 = 0.f, sb1 = 0.f;
#pragma unroll 8
    for (int d = 0; d < 256; d += 2) {
        float w0 = wrow[d], w1 = wrow[d + 1];
        sa0 += w0 * Wa[d * 256 + f];
        sa1 += w1 * Wa[(d + 1) * 256 + f];
        sb0 += w0 * Wb[d * 256 + f];
        sb1 += w1 * Wb[(d + 1) * 256 + f];
    }
    bf16 h, l;
    splitbf(sa0 + sa1, h, l); WfabT_H[(size_t)(2*f)*256 + c] = h;   WfabT_L[(size_t)(2*f)*256 + c] = l;
    splitbf(sb0 + sb1, h, l); WfabT_H[(size_t)(2*f+1)*256 + c] = h; WfabT_L[(size_t)(2*f+1)*256 + c] = l;
}

__global__ void make_bias2(const float* __restrict__ bfv,
                           const float* __restrict__ Wa, const float* __restrict__ ba,
                           const float* __restrict__ Wb, const float* __restrict__ bb) {
    int f = threadIdx.x;
    float sa0 = ba[f], sa1 = 0.f, sb0 = bb[f], sb1 = 0.f;
#pragma unroll 8
    for (int d = 0; d < 256; d += 2) {
        float v0 = bfv[d], v1 = bfv[d + 1];
        sa0 += v0 * Wa[d * 256 + f];
        sa1 += v1 * Wa[(d + 1) * 256 + f];
        sb0 += v0 * Wb[d * 256 + f];
        sb1 += v1 * Wb[(d + 1) * 256 + f];
    }
    g_bfa2[f] = sa0 + sa1; g_bfb2[f] = sb0 + sb1;
}

__global__ void make_vcab(const float* __restrict__ Wa, const float* __restrict__ Wb) {
    int f = blockIdx.x, j = threadIdx.x;
    float sa0 = 0.f, sa1 = 0.f, sb0 = 0.f, sb1 = 0.f;
    if (j < MCLUS) {
#pragma unroll 8
        for (int c = 0; c < 256; c += 2) {
            float v0 = recbf(qkvH, qkvL, (size_t)j * 768 + 512 + c);
            float v1 = recbf(qkvH, qkvL, (size_t)j * 768 + 512 + c + 1);
            sa0 += v0 * Wa[c * 256 + f];
            sa1 += v1 * Wa[(c + 1) * 256 + f];
            sb0 += v0 * Wb[c * 256 + f];
            sb1 += v1 * Wb[(c + 1) * 256 + f];
        }
    }
    bf16 h, l;
    splitbf(sa0 + sa1, h, l); vcabT_H[(2*f)*64 + j] = h;   vcabT_L[(2*f)*64 + j] = l;
    splitbf(sb0 + sb1, h, l); vcabT_H[(2*f+1)*64 + j] = h; vcabT_L[(2*f+1)*64 + j] = l;
}

// ============================================================================
// bf16 planar GEMM. EPI=0: normal. EPI=1: fused gated scorer.
// ============================================================================
#define PSTRIDE 5120
#define STSTRIDE 20480

__device__ __forceinline__ void cp16(unsigned dst, const void* src, bool valid) {
    int sz = valid ? 16 : 0;
    asm volatile("cp.async.cg.shared.global [%0], [%1], 16, %2;\n"
                 :: "r"(dst), "l"(src), "r"(sz));
}
__device__ __forceinline__ void mma_bf16(float* c, const unsigned* a, const unsigned* b) {
    asm volatile(
        "mma.sync.aligned.m16n8k16.row.col.f32.bf16.bf16.f32 "
        "{%0,%1,%2,%3},{%4,%5,%6,%7},{%8,%9},{%0,%1,%2,%3};\n"
        : "+f"(c[0]), "+f"(c[1]), "+f"(c[2]), "+f"(c[3])
        : "r"(a[0]), "r"(a[1]), "r"(a[2]), "r"(a[3]), "r"(b[0]), "r"(b[1]));
}
__device__ __forceinline__ void ldsm4(unsigned* r, unsigned addr) {
    asm volatile("ldmatrix.sync.aligned.m8n8.x4.shared.b16 {%0,%1,%2,%3}, [%4];"
        : "=r"(r[0]), "=r"(r[1]), "=r"(r[2]), "=r"(r[3]) : "r"(addr));
}

__device__ __forceinline__ void stage_tile(
    bf16* sb,
    const bf16* __restrict__ Ahi, const bf16* __restrict__ Alo, int lda, int transA,
    const bf16* __restrict__ Bhi, const bf16* __restrict__ Blo, int ldb, int transB,
    int m0, int n0, int k0, int M, int nBound, int tid)
{
    int r = tid & 127;
    int kh = (tid >> 7) << 4;
    if (!transB) {
        bool v = (n0 + r) < nBound;
        const bf16* gh = v ? (Bhi + (size_t)(n0 + r) * ldb + k0 + kh) : Bhi;
        const bf16* gl = v ? (Blo + (size_t)(n0 + r) * ldb + k0 + kh) : Blo;
        unsigned sh = (unsigned)__cvta_generic_to_shared(sb + 2*PSTRIDE + r*40 + kh);
        unsigned sl = (unsigned)__cvta_generic_to_shared(sb + 3*PSTRIDE + r*40 + kh);
        cp16(sh, gh, v); cp16(sh + 16, gh + 8, v);
        cp16(sl, gl, v); cp16(sl + 16, gl + 8, v);
    } else {
        int n8 = (tid & 15) * 8;
        int kq = tid >> 4;
        bf16 z = __float2bfloat16(0.f);
#pragma unroll
        for (int e = 0; e < 2; e++) {
            int kk = kq + (e << 4);
            const bf16* gh = Bhi + (size_t)(k0 + kk) * ldb + n0 + n8;
            const bf16* gl = Blo + (size_t)(k0 + kk) * ldb + n0 + n8;
            if (n0 + n8 + 7 < nBound) {
                uint4 vh = *(const uint4*)gh;
                uint4 vl = *(const uint4*)gl;
                const bf16* eh = (const bf16*)&vh;
                const bf16* el = (const bf16*)&vl;
#pragma unroll
                for (int j = 0; j < 8; j++) {
                    sb[2*PSTRIDE + (n8+j)*40 + kk] = eh[j];
                    sb[3*PSTRIDE + (n8+j)*40 + kk] = el[j];
                }
            } else {
#pragma unroll
                for (int j = 0; j < 8; j++) {
                    bool ok = (n0 + n8 + j) < nBound;
                    sb[2*PSTRIDE + (n8+j)*40 + kk] = ok ? gh[j] : z;
                    sb[3*PSTRIDE + (n8+j)*40 + kk] = ok ? gl[j] : z;
                }
            }
        }
    }
    if (!transA) {
        bool v = (m0 + r) < M;
        const bf16* gh = v ? (Ahi + (size_t)(m0 + r) * lda + k0 + kh) : Ahi;
        const bf16* gl = v ? (Alo + (size_t)(m0 + r) * lda + k0 + kh) : Alo;
        unsigned sh = (unsigned)__cvta_generic_to_shared(sb + r*40 + kh);
        unsigned sl = (unsigned)__cvta_generic_to_shared(sb + PSTRIDE + r*40 + kh);
        cp16(sh, gh, v); cp16(sh + 16, gh + 8, v);
        cp16(sl, gl, v); cp16(sl + 16, gl + 8, v);
    } else {
        int m8 = (tid & 15) * 8;
        int kq = tid >> 4;
        bf16 z = __float2bfloat16(0.f);
#pragma unroll
        for (int e = 0; e < 2; e++) {
            int kk = kq + (e << 4);
            const bf16* gh = Ahi + (size_t)(k0 + kk) * lda + m0 + m8;
            const bf16* gl = Alo + (size_t)(k0 + kk) * lda + m0 + m8;
            if (m0 + m8 + 7 < lda) {
                uint4 vh = *(const uint4*)gh;
                uint4 vl = *(const uint4*)gl;
                const bf16* eh = (const bf16*)&vh;
                const bf16* el = (const bf16*)&vl;
#pragma unroll
                for (int j = 0; j < 8; j++) {
                    sb[(m8+j)*40 + kk] = eh[j];
                    sb[PSTRIDE + (m8+j)*40 + kk] = el[j];
                }
            } else {
#pragma unroll
                for (int j = 0; j < 8; j++) {
                    bool ok = (m0 + m8 + j) < lda;
                    sb[(m8+j)*40 + kk] = ok ? gh[j] : z;
                    sb[PSTRIDE + (m8+j)*40 + kk] = ok ? gl[j] : z;
                }
            }
        }
    }
}

template<int NPROD, int EPI>
__global__ void __launch_bounds__(256, 2) bf16gemm(
    const bf16* __restrict__ Ahi, const bf16* __restrict__ Alo, int lda, int transA,
    const bf16* __restrict__ Bhi, const bf16* __restrict__ Blo, int ldb, int transB,
    float* __restrict__ Cf, bf16* __restrict__ Chi, bf16* __restrict__ Clo, int ldc,
    int M, int N, int kRange,
    const float* __restrict__ bias, const float* __restrict__ rowScale,
    const float* __restrict__ addSrc, int atomicOut, int nBound)
{
    extern __shared__ bf16 smdyn[];
    int tid = threadIdx.x;
    int w = tid >> 5, lane = tid & 31;
    int wm = w >> 2, wn = w & 3;
    int g = lane >> 2, tig = lane & 3;

    int m0 = blockIdx.y * 128;
    int n0 = blockIdx.x * 128;
    int k0beg = blockIdx.z * kRange;
    int nIter = kRange >> 5;

    unsigned uBase = (unsigned)__cvta_generic_to_shared(smdyn);
    unsigned laneA  = (unsigned)((lane & 15) * 80 + (lane >> 4) * 16);
    unsigned laneB4 = (unsigned)((lane & 7) * 80 + ((lane >> 3) & 1) * 16 + ((lane >> 4) & 1) * 640);

    float acc[4][4][4];
#pragma unroll
    for (int i = 0; i < 4; i++)
#pragma unroll
        for (int j = 0; j < 4; j++)
#pragma unroll
            for (int q = 0; q < 4; q++) acc[i][j][q] = 0.f;

    stage_tile(smdyn, Ahi, Alo, lda, transA, Bhi, Blo, ldb, transB,
               m0, n0, k0beg, M, nBound, tid);
    asm volatile("cp.async.commit_group;\n");

    for (int it = 0; it < nIter; it++) {
        if (it + 1 < nIter) {
            stage_tile(smdyn + ((it+1)&1)*STSTRIDE, Ahi, Alo, lda, transA,
                       Bhi, Blo, ldb, transB, m0, n0, k0beg + (it+1)*32, M, nBound, tid);
            asm volatile("cp.async.commit_group;\n");
            asm volatile("cp.async.wait_group 1;\n");
        } else {
            asm volatile("cp.async.wait_group 0;\n");
        }
        __syncthreads();

        unsigned uB = uBase + (unsigned)((it & 1) * STSTRIDE * 2);
#pragma unroll
        for (int ks = 0; ks < 2; ks++) {
            unsigned kB = (unsigned)(ks * 32);
            unsigned bh[4][2], bl[4][2];
#pragma unroll
            for (int ntp = 0; ntp < 2; ntp++) {
                unsigned ad = uB + (unsigned)(2*PSTRIDE*2 + (wn*32 + ntp*16)*80) + kB + laneB4;
                unsigned t4[4];
                ldsm4(t4, ad);
                bh[2*ntp][0] = t4[0]; bh[2*ntp][1] = t4[1];
                bh[2*ntp+1][0] = t4[2]; bh[2*ntp+1][1] = t4[3];
                ldsm4(t4, ad + PSTRIDE*2);
                bl[2*ntp][0] = t4[0]; bl[2*ntp][1] = t4[1];
                bl[2*ntp+1][0] = t4[2]; bl[2*ntp+1][1] = t4[3];
            }
#pragma unroll
            for (int mt = 0; mt < 4; mt++) {
                unsigned ad = uB + (unsigned)((wm*64 + mt*16)*80) + kB + laneA;
                unsigned ah[4], al[4];
                ldsm4(ah, ad);
                ldsm4(al, ad + PSTRIDE*2);
#pragma unroll
                for (int nt = 0; nt < 4; nt++) {
                    mma_bf16(acc[mt][nt], ah, bh[nt]);
                    mma_bf16(acc[mt][nt], al, bh[nt]);
                    if (NPROD == 3) mma_bf16(acc[mt][nt], ah, bl[nt]);
                }
            }
        }
        __syncthreads();
    }

    if (EPI == 1) {
        float sacc[4][2];
#pragma unroll
        for (int mt = 0; mt < 4; mt++) { sacc[mt][0] = 0.f; sacc[mt][1] = 0.f; }
#pragma unroll
        for (int nt = 0; nt < 4; nt++) {
            int c = n0 + wn * 32 + nt * 8 + tig * 2;
            int f = c >> 1;
            float bav = bias[f], bbv = rowScale[f], wcv = addSrc[f];
#pragma unroll
            for (int mt = 0; mt < 4; mt++) {
#pragma unroll
                for (int h2 = 0; h2 < 2; h2++) {
                    float v0 = acc[mt][nt][h2*2 + 0] + bav;
                    float v1 = acc[mt][nt][h2*2 + 1] + bbv;
                    float p = tanhf(v0) * (1.f / (1.f + expf(-v1))) * wcv;
                    sacc[mt][h2] += p;
                }
            }
        }
#pragma unroll
        for (int mt = 0; mt < 4; mt++) {
#pragma unroll
            for (int h2 = 0; h2 < 2; h2++) {
                float s = sacc[mt][h2];
                s += __shfl_xor_sync(0xffffffffu, s, 1);
                s += __shfl_xor_sync(0xffffffffu, s, 2);
                if (tig == 0) {
                    int r = m0 + wm * 64 + mt * 16 + g + h2 * 8;
                    if (r < M) atomicAdd(&Cf[r], s);
                }
            }
        }
        return;
    }

#pragma unroll
    for (int mt = 0; mt < 4; mt++) {
#pragma unroll
        for (int nt = 0; nt < 4; nt++) {
            int rA = m0 + wm * 64 + mt * 16 + g;
            int c = n0 + wn * 32 + nt * 8 + tig * 2;
            if (c >= N) continue;
#pragma unroll
            for (int h2 = 0; h2 < 2; h2++) {
                int r = rA + h2 * 8;
                if (r >= M) continue;
                float v0 = acc[mt][nt][h2*2 + 0];
                float v1 = acc[mt][nt][h2*2 + 1];
                size_t idx = (size_t)r * ldc + c;
                if (atomicOut) {
                    atomicAdd(&Cf[idx], v0);
                    atomicAdd(&Cf[idx+1], v1);
                    continue;
                }
                if (rowScale) { float rs = rowScale[r]; v0 *= rs; v1 *= rs; }
                if (addSrc) { v0 += addSrc[idx]; v1 += addSrc[idx+1]; }
                if (bias) { v0 += bias[c]; v1 += bias[c+1]; }
                if (Cf) *(float2*)&Cf[idx] = make_float2(v0, v1);
                if (Chi) {
                    __nv_bfloat162 hv, lv;
                    bf16 h, l;
                    splitbf(v0, h, l); hv.x = h; lv.x = l;
                    splitbf(v1, h, l); hv.y = h; lv.y = l;
                    *(__nv_bfloat162*)&Chi[idx] = hv;
                    *(__nv_bfloat162*)&Clo[idx] = lv;
                }
            }
        }
    }
}

// ---------------- small kernels ---------------------------------------------
__global__ void sa_kernel() {
    __shared__ float qrow[DIM], sc[MCLUS], pr[MCLUS];
    int i = blockIdx.x, c = threadIdx.x;
    qrow[c] = recbf(qkvH, qkvL, (size_t)i * 768 + c);
    __syncthreads();
    if (c < MCLUS) {
        float s = 0.f;
        for (int k = 0; k < DIM; k++)
            s += qrow[k] * recbf(qkvH, qkvL, (size_t)c * 768 + 256 + k);
        sc[c] = s * SCALE;
    }
    __syncthreads();
    float m = -1e30f;
    for (int t = 0; t < MCLUS; t++) m = fmaxf(m, sc[t]);
    if (c < MCLUS) pr[c] = expf(sc[c] - m);
    __syncthreads();
    float sum = 0.f;
    for (int t = 0; t < MCLUS; t++) sum += pr[t];
    float o = 0.f;
    for (int t = 0; t < MCLUS; t++) o += pr[t] * recbf(qkvH, qkvL, (size_t)t * 768 + 512 + c);
    g_osc[i * DIM + c] = o / sum;
}

__global__ void cap_rowsoft() {
    int row = blockIdx.x * 8 + (threadIdx.x >> 5);
    int lane = threadIdx.x & 31;
    size_t base = (size_t)row * 64;
    float v1 = (lane < MCLUS) ? g_Scap[base + lane] : -1e30f;
    float v2 = (lane + 32 < MCLUS) ? g_Scap[base + 32 + lane] : -1e30f;
    float m = fmaxf(v1, v2);
#pragma unroll
    for (int o = 16; o; o >>= 1) m = fmaxf(m, __shfl_xor_sync(0xffffffffu, m, o));
    float e1 = (lane < MCLUS) ? expf((v1 - m) * SCALE) : 0.f;
    float e2 = (lane + 32 < MCLUS) ? expf((v2 - m) * SCALE) : 0.f;
    float s = e1 + e2;
#pragma unroll
    for (int o = 16; o; o >>= 1) s += __shfl_xor_sync(0xffffffffu, s, o);
    float inv = 1.f / s;
    bf16 h, l;
    splitbf(e1 * inv, h, l); PH[base + lane] = h; PL[base + lane] = l;
    splitbf(e2 * inv, h, l); PH[base + 32 + lane] = h; PL[base + 32 + lane] = l;
}

__global__ void colmax_part() {
    int col = threadIdx.x & 63, rq = threadIdx.x >> 6;
    float m = -1e30f;
    int r0 = blockIdx.x * 1024;
    for (int r = r0 + rq; r < r0 + 1024; r += 4) m = fmaxf(m, g_Scac[(size_t)r * 64 + col]);
    __shared__ float sm[256];
    sm[threadIdx.x] = m;
    __syncthreads();
    if (rq == 0)
        g_pmax[blockIdx.x * 64 + col] =
            fmaxf(fmaxf(sm[col], sm[64+col]), fmaxf(sm[128+col], sm[192+col]));
}
__global__ void colmax_comb() {
    int col = threadIdx.x;
    float m = -1e30f;
    for (int b = 0; b < 64; b++) m = fmaxf(m, g_pmax[b * 64 + col]);
    g_cmax[col] = m;
}
__global__ void cac_exp() {
    int col = threadIdx.x & 63, rq = threadIdx.x >> 6;
    float mx = g_cmax[col];
    float s = 0.f;
    int r0 = blockIdx.x * 1024;
    for (int r = r0 + rq; r < r0 + 1024; r += 4) {
        float v = g_Scac[(size_t)r * 64 + col];
        float e = (col < MCLUS) ? expf((v - mx) * SCALE) : 0.f;
        bf16 h, l; splitbf(e, h, l);
        EH[(size_t)r * 64 + col] = h; EL[(size_t)r * 64 + col] = l;
        s += e;
    }
    __shared__ float sm[256];
    sm[threadIdx.x] = s;
    __syncthreads();
    if (rq == 0 && col < MCLUS)
        atomicAdd(&g_clsum[col], sm[col] + sm[64+col] + sm[128+col] + sm[192+col]);
}
__global__ void cac_div() {
    int i = blockIdx.x, c = threadIdx.x;
    g_occ[i * DIM + c] /= g_clsum[i];
}

__global__ void linprep_kernel(const float* __restrict__ scale_linear) {
    int i = blockIdx.x, c = threadIdx.x;
    int warp = c >> 5, lane = c & 31;
    size_t tok = (size_t)(MCLUS + i) * 768;
    float sp = logf(1.f + expf(scale_linear[c]));
    float q = recbf(qkvH, qkvL, tok + c);
    float k = recbf(qkvH, qkvL, tok + 256 + c);
    float tq = (fmaxf(q, 0.f) + 1e-6f) / sp;
    float tk = (fmaxf(k, 0.f) + 1e-6f) / sp;
    float uq = tq*tq*tq, uk = tk*tk*tk;
    float r0 = tq*tq, r1 = uq*uq, r2 = tk*tk, r3 = uk*uk;
#pragma unroll
    for (int o = 16; o; o >>= 1) {
        r0 += __shfl_xor_sync(0xffffffffu, r0, o);
        r1 += __shfl_xor_sync(0xffffffffu, r1, o);
        r2 += __shfl_xor_sync(0xffffffffu, r2, o);
        r3 += __shfl_xor_sync(0xffffffffu, r3, o);
    }
    __shared__ float4 wred[8];
    __shared__ float4 tot;
    if (lane == 0) wred[warp] = make_float4(r0, r1, r2, r3);
    __syncthreads();
    if (c == 0) {
        float4 t = wred[0];
#pragma unroll
        for (int wq = 1; wq < 8; wq++) {
            float4 a = wred[wq];
            t.x += a.x; t.y += a.y; t.z += a.z; t.w += a.w;
        }
        tot = t;
    }
    __syncthreads();
    float4 t = tot;
    float vq = uq * sqrtf(t.x) / sqrtf(t.y);
    float vk = uk * sqrtf(t.z) / sqrtf(t.w);
    size_t o = (size_t)i * DIM + c;
    bf16 h, l;
    splitbf(vq, h, l); qlH[o] = h; qlL[o] = l;
    splitbf(vk, h, l); klH[o] = h; klL[o] = l;
}

__global__ void klsum_kernel() {
    int c = threadIdx.x;
    int r0 = blockIdx.x * (NPATH / 256);
    float s = 0.f;
    for (int r = r0; r < r0 + NPATH / 256; r++)
        s += recbf(klH, klL, (size_t)r * DIM + c);
    atomicAdd(&g_klsum[c], s);
}
__global__ void zfac_kernel() {
    int warp = threadIdx.x >> 5, lane = threadIdx.x & 31;
    int row = blockIdx.x * 8 + warp;
    float s = 0.f;
    for (int cc = lane; cc < DIM; cc += 32)
        s += recbf(qlH, qlL, (size_t)row * DIM + cc) * g_klsum[cc];
    for (int o = 16; o; o >>= 1) s += __shfl_down_sync(0xffffffffu, s, o);
    if (!lane) g_zfac[row] = 1.f / (s + 1e-6f);
}

// depthwise 5x5 conv, 4(w) x 8(h) output pixels per block, thread = channel
__global__ void conv_kernel(const float* __restrict__ dwc_w,
                            const float* __restrict__ dwc_b) {
    int d = threadIdx.x;
    int b = blockIdx.x;
    int w0 = (b >> 5) * 4;
    int h0 = (b & 31) * 8;
    float wt[25];
#pragma unroll
    for (int i = 0; i < 25; i++) wt[i] = dwc_w[d * 25 + i];
    float bias = dwc_b[d];
    float acc[4][8];
#pragma unroll
    for (int ow = 0; ow < 4; ow++)
#pragma unroll
        for (int oh = 0; oh < 8; oh++) acc[ow][oh] = bias;

#pragma unroll
    for (int dwa = 0; dwa < 8; dwa++) {
        int wa = w0 + dwa - 2;
        if ((unsigned)wa >= 256u) continue;
#pragma unroll
        for (int dhb = 0; dhb < 12; dhb++) {
            int hb = h0 + dhb - 2;
            if ((unsigned)hb >= 256u) continue;
            float val = recbf(qkvH, qkvL, (size_t)(MCLUS + wa * 256 + hb) * 768 + 512 + d);
#pragma unroll
            for (int ow = 0; ow < 4; ow++) {
                int a = dwa - ow;
                if (a < 0 || a > 4) continue;
#pragma unroll
                for (int oh = 0; oh < 8; oh++) {
                    int bo = dhb - oh;
                    if (bo < 0 || bo > 4) continue;
                    acc[ow][oh] += val * wt[a * 5 + bo];
                }
            }
        }
    }
#pragma unroll
    for (int ow = 0; ow < 4; ow++)
#pragma unroll
        for (int oh = 0; oh < 8; oh++)
            g_spin[(size_t)((w0 + ow) * 256 + h0 + oh) * DIM + d] = acc[ow][oh];
}

__global__ void gated_kernel(const float* __restrict__ T, int nrows,
                             const float* __restrict__ Wa, const float* __restrict__ ba,
                             const float* __restrict__ Wb, const float* __restrict__ bb,
                             const float* __restrict__ Wc,
                             float* __restrict__ Aout)
{
    __shared__ float ts[16 * DIM];
    int c = threadIdx.x;
    int row0 = blockIdx.x * 16;
#pragma unroll
    for (int r = 0; r < 16; r++)
        ts[r * DIM + c] = (row0 + r < nrows) ? T[(size_t)(row0 + r) * DIM + c] : 0.f;
    __syncthreads();
    float aa[16], gg[16];
    float bav = ba[c], bbv = bb[c];
#pragma unroll
    for (int r = 0; r < 16; r++) { aa[r] = bav; gg[r] = bbv; }
    for (int k = 0; k < DIM; k++) {
        float wa = Wa[k * DIM + c];
        float wb = Wb[k * DIM + c];
#pragma unroll
        for (int r = 0; r < 16; r++) {
            float t = ts[r * DIM + k];
            aa[r] += t * wa; gg[r] += t * wb;
        }
    }
    float wcv = Wc[c];
    __syncthreads();
#pragma unroll
    for (int r = 0; r < 16; r++) {
        float a = tanhf(aa[r]);
        float g2 = 1.f / (1.f + expf(-gg[r]));
        ts[r * DIM + c] = a * g2 * wcv;
    }
    __syncthreads();
    int wid = c >> 5, lane = c & 31;
    for (int r = wid; r < 16; r += 8) {
        float s = 0.f;
        for (int cc = lane; cc < DIM; cc += 32) s += ts[r * DIM + cc];
#pragma unroll
        for (int o = 16; o; o >>= 1) s += __shfl_down_sync(0xffffffffu, s, o);
        if (!lane && row0 + r < nrows) Aout[row0 + r] = s;
    }
}

// small-n single block max
__global__ void fmax_kernel(const float* __restrict__ A, int n, int slot) {
    __shared__ float red[256];
    int t = threadIdx.x;
    float m = -1e30f;
    for (int r = t; r < n; r += 256) m = fmaxf(m, A[r]);
    red[t] = m;
    __syncthreads();
    for (int s = 128; s > 0; s >>= 1) {
        if (t < s) red[t] = fmaxf(red[t], red[t + s]);
        __syncthreads();
    }
    if (!t) g_fmax[slot] = red[0];
}

// big-n two-pass max: 256 blocks -> g_fpart, then combine
__global__ void fmax_part(const float* __restrict__ A, int pslot) {
    int i = blockIdx.x * 256 + threadIdx.x;
    float m = A[i];
    int lane = threadIdx.x & 31, warp = threadIdx.x >> 5;
#pragma unroll
    for (int o = 16; o; o >>= 1) m = fmaxf(m, __shfl_xor_sync(0xffffffffu, m, o));
    __shared__ float wred[8];
    if (lane == 0) wred[warp] = m;
    __syncthreads();
    if (threadIdx.x == 0) {
        float mm = wred[0];
#pragma unroll
        for (int wq = 1; wq < 8; wq++) mm = fmaxf(mm, wred[wq]);
        g_fpart[pslot * 256 + blockIdx.x] = mm;
    }
}
__global__ void fmax_comb(int pslot, int slot) {
    int t = threadIdx.x;
    float m = g_fpart[pslot * 256 + t];
    int lane = t & 31, warp = t >> 5;
#pragma unroll
    for (int o = 16; o; o >>= 1) m = fmaxf(m, __shfl_xor_sync(0xffffffffu, m, o));
    __shared__ float wred[8];
    if (lane == 0) wred[warp] = m;
    __syncthreads();
    if (t == 0) {
        float mm = wred[0];
#pragma unroll
        for (int wq = 1; wq < 8; wq++) mm = fmaxf(mm, wred[wq]);
        g_fmax[slot] = mm;
    }
}

__global__ void wsum_kernel(const float* __restrict__ A, const float* __restrict__ X,
                            int n, int slot, int rpb) {
    __shared__ float se[256];
    int c = threadIdx.x;
    int start = blockIdx.x * rpb;
    int end = min(n, start + rpb);
    float mx = g_fmax[slot];
    float h = 0.f, lpart = 0.f;
    for (int r0 = start; r0 < end; r0 += 256) {
        int cnt = min(256, end - r0);
        if (c < cnt) se[c] = expf(A[r0 + c] - mx);
        __syncthreads();
        for (int t = 0; t < cnt; t++) h += se[t] * X[(size_t)(r0 + t) * DIM + c];
        if (c == 0) for (int t = 0; t < cnt; t++) lpart += se[t];
        __syncthreads();
    }
    atomicAdd(&g_fh[slot * DIM + c], h);
    if (c == 0) atomicAdd(&g_fl[slot], lpart);
}

__global__ void wsum_planes(const float* __restrict__ A,
                            const bf16* __restrict__ XH, const bf16* __restrict__ XL,
                            int n, int slot, int rpb, int width, float* __restrict__ outv) {
    __shared__ float se[256];
    int c = threadIdx.x;
    int start = blockIdx.x * rpb;
    int end = min(n, start + rpb);
    float mx = g_fmax[slot];
    float h = 0.f, lpart = 0.f;
    for (int r0 = start; r0 < end; r0 += 256) {
        int cnt = min(256, end - r0);
        if (c < cnt) se[c] = expf(A[r0 + c] - mx);
        __syncthreads();
        if (c < width)
            for (int t = 0; t < cnt; t++) {
                size_t idx = (size_t)(r0 + t) * width + c;
                h += se[t] * (__bfloat162float(XH[idx]) + __bfloat162float(XL[idx]));
            }
        if (c == 0) for (int t = 0; t < cnt; t++) lpart += se[t];
        __syncthreads();
    }
    if (c < width) atomicAdd(&outv[c], h);
    if (c == 0) atomicAdd(&g_fl[slot], lpart);
}

__global__ void post_cross() {
    int c = threadIdx.x;
    float s = 0.f;
    for (int j = 0; j < MCLUS; j++)
        s += g_fw[j] * recbf(qkvH, qkvL, (size_t)j * 768 + 512 + c);
    g_fh[1 * DIM + c] = s;
}
__global__ void post_self(const float* __restrict__ Wf, const float* __restrict__ bfv) {
    int c = threadIdx.x;
    float s0 = 0.f, s1 = 0.f;
#pragma unroll 8
    for (int d = 0; d < 256; d += 2) {
        s0 += g_ft[d] * Wf[d * 256 + c];
        s1 += g_ft[d + 1] * Wf[(d + 1) * 256 + c];
    }
    g_fh[3 * DIM + c] = s0 + s1 + bfv[c] * g_fl[3];
}

__global__ void fuse_final(const float* __restrict__ W1, const float* __restrict__ b1,
                           const float* __restrict__ W2, const float* __restrict__ b2,
                           const float* __restrict__ W3a, const float* __restrict__ b3a,
                           const float* __restrict__ W3b, const float* __restrict__ b3b,
                           float* __restrict__ out)
{
    __shared__ float v0[DIM], v1[DIM], hb2[2 * DIM], ub[DIM];
    int f = blockIdx.x, c = threadIdx.x;
    int s0 = f * 2, s1 = f * 2 + 1;
    v0[c] = g_fh[s0 * DIM + c] / g_fl[s0];
    v1[c] = g_fh[s1 * DIM + c] / g_fl[s1];
    __syncthreads();
    float h1 = b1[c], h2 = b2[c];
    for (int k = 0; k < DIM; k++) {
        h1 += v0[k] * W1[k * DIM + c];
        h2 += v1[k] * W2[k * DIM + c];
    }
    hb2[c] = fmaxf(h1, 0.f);
    hb2[DIM + c] = fmaxf(h2, 0.f);
    __syncthreads();
    float u = b3a[c];
    for (int k = 0; k < 2 * DIM; k++) u += hb2[k] * W3a[k * DIM + c];
    ub[c] = fmaxf(u, 0.f);
    __syncthreads();
    float o = b3b[c];
    for (int k = 0; k < DIM; k++) o += ub[k] * W3b[k * DIM + c];
    out[f * DIM + c] = fmaxf(o, 0.f);
}

// ---------------------------------------------------------------------------
extern "C" void kernel_launch(void* const* d_in, const int* in_sizes, int n_in,
                              void* d_out, int out_size) {
    const float* x   = (const float*)d_in[0];
    const float* Wqkv= (const float*)d_in[1];
    const float* scl = (const float*)d_in[2];
    const float* dwcw= (const float*)d_in[3];
    const float* dwcb= (const float*)d_in[4];
    const float* Wa  = (const float*)d_in[5];
    const float* ba  = (const float*)d_in[6];
    const float* Wb  = (const float*)d_in[7];
    const float* bb  = (const float*)d_in[8];
    const float* Wc  = (const float*)d_in[9];
    const float* W1  = (const float*)d_in[11];
    const float* b1  = (const float*)d_in[12];
    const float* W2  = (const float*)d_in[13];
    const float* b2  = (const float*)d_in[14];
    const float* W3a = (const float*)d_in[15];
    const float* b3a = (const float*)d_in[16];
    const float* W3b = (const float*)d_in[17];
    const float* b3b = (const float*)d_in[18];
    const float* Wf  = (const float*)d_in[19];
    const float* bf  = (const float*)d_in[20];
    float* out = (float*)d_out;

    cudaFuncSetAttribute(bf16gemm<3,0>, cudaFuncAttributeMaxDynamicSharedMemorySize, 81920);
    cudaFuncSetAttribute(bf16gemm<2,0>, cudaFuncAttributeMaxDynamicSharedMemorySize, 81920);
    cudaFuncSetAttribute(bf16gemm<2,1>, cudaFuncAttributeMaxDynamicSharedMemorySize, 81920);
    const int SM = 81920;

#define SYM(p, s) float* p; cudaGetSymbolAddress((void**)&p, s)
    SYM(p_kv, g_kv);
    SYM(p_spin, g_spin); SYM(p_zfac, g_zfac);
    SYM(p_occ, g_occ); SYM(p_osc, g_osc);
    SYM(p_Acp, g_Acp); SYM(p_Asp, g_Asp); SYM(p_Acc, g_Acc); SYM(p_Asc, g_Asc);
    SYM(p_Scap, g_Scap); SYM(p_Scac, g_Scac);
    SYM(p_fw, g_fw); SYM(p_ft, g_ft);
    SYM(p_bfa2, g_bfa2); SYM(p_bfb2, g_bfb2);
#define BSYM(p, s) bf16* p; cudaGetSymbolAddress((void**)&p, s)
    BSYM(b_qkvH, qkvH); BSYM(b_qkvL, qkvL); BSYM(b_xH, xH); BSYM(b_xL, xL);
    BSYM(b_WqT_H, WqkvT_H); BSYM(b_WqT_L, WqkvT_L);
    BSYM(b_vcabT_H, vcabT_H); BSYM(b_vcabT_L, vcabT_L);
    BSYM(b_WfabT_H, WfabT_H); BSYM(b_WfabT_L, WfabT_L);
    BSYM(b_kvT_H, kvT_H); BSYM(b_kvT_L, kvT_L);
    BSYM(b_qlH, qlH); BSYM(b_qlL, qlL); BSYM(b_klH, klH); BSYM(b_klL, klL);
    BSYM(b_PH, PH); BSYM(b_PL, PL); BSYM(b_EH, EH); BSYM(b_EL, EL);
    BSYM(b_spinH, spinH); BSYM(b_spinL, spinL);

    const bf16* vpH = b_qkvH + (size_t)MCLUS * 768 + 512;
    const bf16* vpL = b_qkvL + (size_t)MCLUS * 768 + 512;

    // launches 1-3, qkv GEMM at #4 (ncu capture slot)
    init_kernel<<<64, 256>>>();
    cvt_planar<<<(NTOK * 256 / 4 + 255) / 256, 256>>>(x, b_xH, b_xL, NTOK * 256);
    transpose_cvt<<<dim3(8, 24), dim3(32, 8)>>>(Wqkv, 768, 256, 768, 256, b_WqT_H, b_WqT_L, 1, 0);

    // #4: qkv = x @ Wqkv -> planes only
    bf16gemm<3,0><<<dim3(6, 513), 256, SM>>>(b_xH, b_xL, 256, 0, b_WqT_H, b_WqT_L, 256, 0,
        nullptr, b_qkvH, b_qkvL, 768, NTOK, 768, 256, nullptr, nullptr, nullptr, 0, 768);

    make_wfab<<<256, 256>>>(Wf, Wa, Wb);
    make_bias2<<<1, 256>>>(bf, Wa, ba, Wb, bb);
    sa_kernel<<<MCLUS, 256>>>();
    make_vcab<<<256, 64>>>(Wa, Wb);

    // cap: S = qp @ kc^T (2-prod), row softmax -> P planes
    bf16gemm<2,0><<<dim3(1, 512), 256, SM>>>(b_qkvH + (size_t)MCLUS * 768, b_qkvL + (size_t)MCLUS * 768, 768, 0,
        b_qkvH + 256, b_qkvL + 256, 768, 0, p_Scap, nullptr, nullptr, 64,
        NPATH, 64, 256, nullptr, nullptr, nullptr, 0, MCLUS);
    cap_rowsoft<<<NPATH / 8, 256>>>();

    // cac: S2 = kp @ qc^T (2-prod), col softmax, occ = E^T @ vp / l
    bf16gemm<2,0><<<dim3(1, 512), 256, SM>>>(b_qkvH + (size_t)MCLUS * 768 + 256, b_qkvL + (size_t)MCLUS * 768 + 256, 768, 0,
        b_qkvH, b_qkvL, 768, 0, p_Scac, nullptr, nullptr, 64,
        NPATH, 64, 256, nullptr, nullptr, nullptr, 0, MCLUS);
    colmax_part<<<64, 256>>>();
    colmax_comb<<<1, 64>>>();
    cac_exp<<<64, 256>>>();
    bf16gemm<3,0><<<dim3(2, 1, 32), 256, SM>>>(b_EH, b_EL, 64, 1, vpH, vpL, 768, 1,
        p_occ, nullptr, nullptr, 256, MCLUS, 256, 2048, nullptr, nullptr, nullptr, 1, 256);
    cac_div<<<MCLUS, 256>>>();

    // linear attention
    linprep_kernel<<<NPATH, 256>>>(scl);
    klsum_kernel<<<256, 256>>>();
    zfac_kernel<<<NPATH / 8, 256>>>();
    bf16gemm<3,0><<<dim3(2, 2, 32), 256, SM>>>(b_klH, b_klL, 256, 1, vpH, vpL, 768, 1,
        p_kv, nullptr, nullptr, 256, 256, 256, 2048, nullptr, nullptr, nullptr, 1, 256);
    transpose_cvt<<<dim3(8, 8), dim3(32, 8)>>>(p_kv, 256, 256, 256, 256, b_kvT_H, b_kvT_L, 1, 0);

    conv_kernel<<<2048, 256>>>(dwcw, dwcb);
    // spin = zfac * (ql @ kv) + fm  (planes only)
    bf16gemm<3,0><<<dim3(2, 512), 256, SM>>>(b_qlH, b_qlL, 256, 0, b_kvT_H, b_kvT_L, 256, 0,
        nullptr, b_spinH, b_spinL, 256, NPATH, 256, 256, nullptr, p_zfac, p_spin, 0, 256);

    // small gated scorers (fp32)
    gated_kernel<<<4, 256>>>(p_occ, MCLUS, Wa, ba, Wb, bb, Wc, p_Acc);
    gated_kernel<<<4, 256>>>(p_osc, MCLUS, Wa, ba, Wb, bb, Wc, p_Asc);

    // fused gated cross/self
    bf16gemm<2,1><<<dim3(4, 512), 256, SM>>>(b_PH, b_PL, 64, 0, b_vcabT_H, b_vcabT_L, 64, 0,
        p_Acp, nullptr, nullptr, 0, NPATH, 512, 64, ba, bb, Wc, 0, 512);
    bf16gemm<2,1><<<dim3(4, 512), 256, SM>>>(b_spinH, b_spinL, 256, 0, b_WfabT_H, b_WfabT_L, 256, 0,
        p_Asp, nullptr, nullptr, 0, NPATH, 512, 256, p_bfa2, p_bfb2, Wc, 0, 512);

    // fusion pooling (big maxima now two-pass multi-block)
    fmax_kernel<<<1, 256>>>(p_Acc, MCLUS, 0);
    fmax_kernel<<<1, 256>>>(p_Asc, MCLUS, 2);
    fmax_part<<<256, 256>>>(p_Acp, 0);
    fmax_part<<<256, 256>>>(p_Asp, 1);
    fmax_comb<<<1, 256>>>(0, 1);
    fmax_comb<<<1, 256>>>(1, 3);
    wsum_kernel<<<1, 256>>>(p_Acc, p_occ, MCLUS, 0, MCLUS);
    wsum_kernel<<<1, 256>>>(p_Asc, p_osc, MCLUS, 2, MCLUS);
    wsum_planes<<<256, 256>>>(p_Acp, b_PH, b_PL, NPATH, 1, 256, 64, p_fw);
    wsum_planes<<<256, 256>>>(p_Asp, b_spinH, b_spinL, NPATH, 3, 256, 256, p_ft);
    post_cross<<<1, 256>>>();
    post_self<<<1, 256>>>(Wf, bf);

    fuse_final<<<2, 256>>>(W1, b1, W2, b2, W3a, b3a, W3b, b3b, out);
}

// round 15
// speedup vs baseline: 1.4564x; 1.4564x over previous
#include <cuda_runtime.h>
#include <cuda_bf16.h>
#include <math.h>
#include <stdint.h>

#define NTOK   65586
#define MCLUS  50
#define NPATH  65536
#define DIM    256
#define SCALE  0.0625f

typedef __nv_bfloat16 bf16;

// ---------------- fp32 scratch ----------------------------------------------
__device__ float g_osc[MCLUS * DIM];
__device__ float g_occ[MCLUS * DIM];
__device__ float g_klsum[DIM];
__device__ float g_kv[DIM * DIM];
__device__ float g_zfac[NPATH];
__device__ float g_spin[(size_t)NPATH * DIM];
__device__ float g_Scap[(size_t)NPATH * 64];
__device__ float g_Scac[(size_t)NPATH * 64];
__device__ float g_pmax[64 * 64];
__device__ float g_cmax[64];
__device__ float g_clsum[64];
__device__ float g_Acp[NPATH];
__device__ float g_Asp[NPATH];
__device__ float g_Acc[MCLUS];
__device__ float g_Asc[MCLUS];
__device__ float g_fpart[2 * 256];
__device__ float g_fmax[4];
__device__ float g_fl[4];
__device__ float g_fh[4 * DIM];
__device__ float g_fw[64];
__device__ float g_ft[DIM];
__device__ float g_bfa2[DIM];
__device__ float g_bfb2[DIM];

// ---------------- bf16 hi/lo planes -----------------------------------------
__device__ __align__(16) bf16 qkvH[(size_t)NTOK * 768], qkvL[(size_t)NTOK * 768];
__device__ __align__(16) bf16 xH[(size_t)NTOK * 256],  xL[(size_t)NTOK * 256];
__device__ __align__(16) bf16 WqkvT_H[768 * 256], WqkvT_L[768 * 256];
__device__ __align__(16) bf16 vcabT_H[512 * 64], vcabT_L[512 * 64];
__device__ __align__(16) bf16 WfabT_H[(size_t)512 * 256], WfabT_L[(size_t)512 * 256];
__device__ __align__(16) bf16 kvT_H[256 * 256], kvT_L[256 * 256];
__device__ __align__(16) bf16 qlH[(size_t)NPATH * 256], qlL[(size_t)NPATH * 256];
__device__ __align__(16) bf16 klH[(size_t)NPATH * 256], klL[(size_t)NPATH * 256];
__device__ __align__(16) bf16 PH[(size_t)NPATH * 64],  PL[(size_t)NPATH * 64];
__device__ __align__(16) bf16 EH[(size_t)NPATH * 64],  EL[(size_t)NPATH * 64];
__device__ __align__(16) bf16 spinH[(size_t)NPATH * 256], spinL[(size_t)NPATH * 256];

__device__ __forceinline__ void splitbf(float v, bf16& h, bf16& l) {
    h = __float2bfloat16(v);
    l = __float2bfloat16(v - __bfloat162float(h));
}
__device__ __forceinline__ float recbf(const bf16* H, const bf16* L, size_t i) {
    return __bfloat162float(H[i]) + __bfloat162float(L[i]);
}

__global__ void init_kernel() {
    int t = blockIdx.x * 256 + threadIdx.x;
    int nthr = gridDim.x * 256;
    for (int i = t; i < NPATH; i += nthr) { g_Acp[i] = 0.f; g_Asp[i] = 0.f; }
    if (blockIdx.x == 0) {
        int c = threadIdx.x;
        for (int i = c; i < DIM * DIM; i += 256) g_kv[i] = 0.f;
        for (int i = c; i < MCLUS * DIM; i += 256) g_occ[i] = 0.f;
        if (c < DIM) { g_klsum[c] = 0.f; g_ft[c] = 0.f; }
        if (c < 64) { g_clsum[c] = 0.f; g_fw[c] = 0.f; }
        if (c < 4) g_fl[c] = 0.f;
        for (int i = c; i < 4 * DIM; i += 256) g_fh[i] = 0.f;
    }
}

__global__ void cvt_planar(const float* __restrict__ src, bf16* __restrict__ h,
                           bf16* __restrict__ l, int n) {
    int i = (blockIdx.x * 256 + threadIdx.x) * 4;
    if (i >= n) return;
    float4 v = *(const float4*)(src + i);
    bf16 a, b;
    splitbf(v.x, a, b); h[i+0]=a; l[i+0]=b;
    splitbf(v.y, a, b); h[i+1]=a; l[i+1]=b;
    splitbf(v.z, a, b); h[i+2]=a; l[i+2]=b;
    splitbf(v.w, a, b); h[i+3]=a; l[i+3]=b;
}

__global__ void transpose_cvt(const float* __restrict__ src, int ldsrc,
                              int R, int C, int Rpad,
                              bf16* __restrict__ dH, bf16* __restrict__ dL,
                              int rowMul, int rowOff) {
    __shared__ float t[32][33];
    int r0 = blockIdx.x * 32, c0 = blockIdx.y * 32;
    int tx = threadIdx.x, ty = threadIdx.y;
    for (int i = ty; i < 32; i += 8) {
        int r = r0 + i, c = c0 + tx;
        t[i][tx] = (r < R && c < C) ? src[(size_t)r * ldsrc + c] : 0.f;
    }
    __syncthreads();
    for (int i = ty; i < 32; i += 8) {
        int c = c0 + i, r = r0 + tx;
        if (c < C && r < Rpad) {
            bf16 h, l; splitbf(t[tx][i], h, l);
            size_t o = (size_t)(c * rowMul + rowOff) * Rpad + r;
            dH[o] = h; dL[o] = l;
        }
    }
}

__global__ void make_wfab(const float* __restrict__ Wf,
                          const float* __restrict__ Wa, const float* __restrict__ Wb) {
    __shared__ float wrow[256];
    int c = blockIdx.x, f = threadIdx.x;
    wrow[f] = Wf[c * 256 + f];
    __syncthreads();
    float sa0 = 0.f, sa1 = 0.f, sb0 = 0.f, sb1 = 0.f;
#pragma unroll 8
    for (int d = 0; d < 256; d += 2) {
        float w0 = wrow[d], w1 = wrow[d + 1];
        sa0 += w0 * Wa[d * 256 + f];
        sa1 += w1 * Wa[(d + 1) * 256 + f];
        sb0 += w0 * Wb[d * 256 + f];
        sb1 += w1 * Wb[(d + 1) * 256 + f];
    }
    bf16 h, l;
    splitbf(sa0 + sa1, h, l); WfabT_H[(size_t)(2*f)*256 + c] = h;   WfabT_L[(size_t)(2*f)*256 + c] = l;
    splitbf(sb0 + sb1, h, l); WfabT_H[(size_t)(2*f+1)*256 + c] = h; WfabT_L[(size_t)(2*f+1)*256 + c] = l;
}

__global__ void make_bias2(const float* __restrict__ bfv,
                           const float* __restrict__ Wa, const float* __restrict__ ba,
                           const float* __restrict__ Wb, const float* __restrict__ bb) {
    int f = threadIdx.x;
    float sa0 = ba[f], sa1 = 0.f, sb0 = bb[f], sb1 = 0.f;
#pragma unroll 8
    for (int d = 0; d < 256; d += 2) {
        float v0 = bfv[d], v1 = bfv[d + 1];
        sa0 += v0 * Wa[d * 256 + f];
        sa1 += v1 * Wa[(d + 1) * 256 + f];
        sb0 += v0 * Wb[d * 256 + f];
        sb1 += v1 * Wb[(d + 1) * 256 + f];
    }
    g_bfa2[f] = sa0 + sa1; g_bfb2[f] = sb0 + sb1;
}

__global__ void make_vcab(const float* __restrict__ Wa, const float* __restrict__ Wb) {
    int f = blockIdx.x, j = threadIdx.x;
    float sa0 = 0.f, sa1 = 0.f, sb0 = 0.f, sb1 = 0.f;
    if (j < MCLUS) {
#pragma unroll 8
        for (int c = 0; c < 256; c += 2) {
            float v0 = recbf(qkvH, qkvL, (size_t)j * 768 + 512 + c);
            float v1 = recbf(qkvH, qkvL, (size_t)j * 768 + 512 + c + 1);
            sa0 += v0 * Wa[c * 256 + f];
            sa1 += v1 * Wa[(c + 1) * 256 + f];
            sb0 += v0 * Wb[c * 256 + f];
            sb1 += v1 * Wb[(c + 1) * 256 + f];
        }
    }
    bf16 h, l;
    splitbf(sa0 + sa1, h, l); vcabT_H[(2*f)*64 + j] = h;   vcabT_L[(2*f)*64 + j] = l;
    splitbf(sb0 + sb1, h, l); vcabT_H[(2*f+1)*64 + j] = h; vcabT_L[(2*f+1)*64 + j] = l;
}

// ============================================================================
// bf16 planar GEMM. EPI=0: normal. EPI=1: fused gated scorer.
// ============================================================================
#define PSTRIDE 5120
#define STSTRIDE 20480

__device__ __forceinline__ void cp16(unsigned dst, const void* src, bool valid) {
    int sz = valid ? 16 : 0;
    asm volatile("cp.async.cg.shared.global [%0], [%1], 16, %2;\n"
                 :: "r"(dst), "l"(src), "r"(sz));
}
__device__ __forceinline__ void mma_bf16(float* c, const unsigned* a, const unsigned* b) {
    asm volatile(
        "mma.sync.aligned.m16n8k16.row.col.f32.bf16.bf16.f32 "
        "{%0,%1,%2,%3},{%4,%5,%6,%7},{%8,%9},{%0,%1,%2,%3};\n"
        : "+f"(c[0]), "+f"(c[1]), "+f"(c[2]), "+f"(c[3])
        : "r"(a[0]), "r"(a[1]), "r"(a[2]), "r"(a[3]), "r"(b[0]), "r"(b[1]));
}
__device__ __forceinline__ void ldsm4(unsigned* r, unsigned addr) {
    asm volatile("ldmatrix.sync.aligned.m8n8.x4.shared.b16 {%0,%1,%2,%3}, [%4];"
        : "=r"(r[0]), "=r"(r[1]), "=r"(r[2]), "=r"(r[3]) : "r"(addr));
}

__device__ __forceinline__ void stage_tile(
    bf16* sb,
    const bf16* __restrict__ Ahi, const bf16* __restrict__ Alo, int lda, int transA,
    const bf16* __restrict__ Bhi, const bf16* __restrict__ Blo, int ldb, int transB,
    int m0, int n0, int k0, int M, int nBound, int tid)
{
    int r = tid & 127;
    int kh = (tid >> 7) << 4;
    if (!transB) {
        bool v = (n0 + r) < nBound;
        const bf16* gh = v ? (Bhi + (size_t)(n0 + r) * ldb + k0 + kh) : Bhi;
        const bf16* gl = v ? (Blo + (size_t)(n0 + r) * ldb + k0 + kh) : Blo;
        unsigned sh = (unsigned)__cvta_generic_to_shared(sb + 2*PSTRIDE + r*40 + kh);
        unsigned sl = (unsigned)__cvta_generic_to_shared(sb + 3*PSTRIDE + r*40 + kh);
        cp16(sh, gh, v); cp16(sh + 16, gh + 8, v);
        cp16(sl, gl, v); cp16(sl + 16, gl + 8, v);
    } else {
        int n8 = (tid & 15) * 8;
        int kq = tid >> 4;
        bf16 z = __float2bfloat16(0.f);
#pragma unroll
        for (int e = 0; e < 2; e++) {
            int kk = kq + (e << 4);
            const bf16* gh = Bhi + (size_t)(k0 + kk) * ldb + n0 + n8;
            const bf16* gl = Blo + (size_t)(k0 + kk) * ldb + n0 + n8;
            if (n0 + n8 + 7 < nBound) {
                uint4 vh = *(const uint4*)gh;
                uint4 vl = *(const uint4*)gl;
                const bf16* eh = (const bf16*)&vh;
                const bf16* el = (const bf16*)&vl;
#pragma unroll
                for (int j = 0; j < 8; j++) {
                    sb[2*PSTRIDE + (n8+j)*40 + kk] = eh[j];
                    sb[3*PSTRIDE + (n8+j)*40 + kk] = el[j];
                }
            } else {
#pragma unroll
                for (int j = 0; j < 8; j++) {
                    bool ok = (n0 + n8 + j) < nBound;
                    sb[2*PSTRIDE + (n8+j)*40 + kk] = ok ? gh[j] : z;
                    sb[3*PSTRIDE + (n8+j)*40 + kk] = ok ? gl[j] : z;
                }
            }
        }
    }
    if (!transA) {
        bool v = (m0 + r) < M;
        const bf16* gh = v ? (Ahi + (size_t)(m0 + r) * lda + k0 + kh) : Ahi;
        const bf16* gl = v ? (Alo + (size_t)(m0 + r) * lda + k0 + kh) : Alo;
        unsigned sh = (unsigned)__cvta_generic_to_shared(sb + r*40 + kh);
        unsigned sl = (unsigned)__cvta_generic_to_shared(sb + PSTRIDE + r*40 + kh);
        cp16(sh, gh, v); cp16(sh + 16, gh + 8, v);
        cp16(sl, gl, v); cp16(sl + 16, gl + 8, v);
    } else {
        int m8 = (tid & 15) * 8;
        int kq = tid >> 4;
        bf16 z = __float2bfloat16(0.f);
#pragma unroll
        for (int e = 0; e < 2; e++) {
            int kk = kq + (e << 4);
            const bf16* gh = Ahi + (size_t)(k0 + kk) * lda + m0 + m8;
            const bf16* gl = Alo + (size_t)(k0 + kk) * lda + m0 + m8;
            if (m0 + m8 + 7 < lda) {
                uint4 vh = *(const uint4*)gh;
                uint4 vl = *(const uint4*)gl;
                const bf16* eh = (const bf16*)&vh;
                const bf16* el = (const bf16*)&vl;
#pragma unroll
                for (int j = 0; j < 8; j++) {
                    sb[(m8+j)*40 + kk] = eh[j];
                    sb[PSTRIDE + (m8+j)*40 + kk] = el[j];
                }
            } else {
#pragma unroll
                for (int j = 0; j < 8; j++) {
                    bool ok = (m0 + m8 + j) < lda;
                    sb[(m8+j)*40 + kk] = ok ? gh[j] : z;
                    sb[PSTRIDE + (m8+j)*40 + kk] = ok ? gl[j] : z;
                }
            }
        }
    }
}

template<int NPROD, int EPI>
__global__ void __launch_bounds__(256, 2) bf16gemm(
    const bf16* __restrict__ Ahi, const bf16* __restrict__ Alo, int lda, int transA,
    const bf16* __restrict__ Bhi, const bf16* __restrict__ Blo, int ldb, int transB,
    float* __restrict__ Cf, bf16* __restrict__ Chi, bf16* __restrict__ Clo, int ldc,
    int M, int N, int kRange,
    const float* __restrict__ bias, const float* __restrict__ rowScale,
    const float* __restrict__ addSrc, int atomicOut, int nBound)
{
    extern __shared__ bf16 smdyn[];
    int tid = threadIdx.x;
    int w = tid >> 5, lane = tid & 31;
    int wm = w >> 2, wn = w & 3;
    int g = lane >> 2, tig = lane & 3;

    int m0 = blockIdx.y * 128;
    int n0 = blockIdx.x * 128;
    int k0beg = blockIdx.z * kRange;
    int nIter = kRange >> 5;

    unsigned uBase = (unsigned)__cvta_generic_to_shared(smdyn);
    unsigned laneA  = (unsigned)((lane & 15) * 80 + (lane >> 4) * 16);
    unsigned laneB4 = (unsigned)((lane & 7) * 80 + ((lane >> 3) & 1) * 16 + ((lane >> 4) & 1) * 640);

    float acc[4][4][4];
#pragma unroll
    for (int i = 0; i < 4; i++)
#pragma unroll
        for (int j = 0; j < 4; j++)
#pragma unroll
            for (int q = 0; q < 4; q++) acc[i][j][q] = 0.f;

    stage_tile(smdyn, Ahi, Alo, lda, transA, Bhi, Blo, ldb, transB,
               m0, n0, k0beg, M, nBound, tid);
    asm volatile("cp.async.commit_group;\n");

    for (int it = 0; it < nIter; it++) {
        if (it + 1 < nIter) {
            stage_tile(smdyn + ((it+1)&1)*STSTRIDE, Ahi, Alo, lda, transA,
                       Bhi, Blo, ldb, transB, m0, n0, k0beg + (it+1)*32, M, nBound, tid);
            asm volatile("cp.async.commit_group;\n");
            asm volatile("cp.async.wait_group 1;\n");
        } else {
            asm volatile("cp.async.wait_group 0;\n");
        }
        __syncthreads();

        unsigned uB = uBase + (unsigned)((it & 1) * STSTRIDE * 2);
#pragma unroll
        for (int ks = 0; ks < 2; ks++) {
            unsigned kB = (unsigned)(ks * 32);
            unsigned bh[4][2], bl[4][2];
#pragma unroll
            for (int ntp = 0; ntp < 2; ntp++) {
                unsigned ad = uB + (unsigned)(2*PSTRIDE*2 + (wn*32 + ntp*16)*80) + kB + laneB4;
                unsigned t4[4];
                ldsm4(t4, ad);
                bh[2*ntp][0] = t4[0]; bh[2*ntp][1] = t4[1];
                bh[2*ntp+1][0] = t4[2]; bh[2*ntp+1][1] = t4[3];
                ldsm4(t4, ad + PSTRIDE*2);
                bl[2*ntp][0] = t4[0]; bl[2*ntp][1] = t4[1];
                bl[2*ntp+1][0] = t4[2]; bl[2*ntp+1][1] = t4[3];
            }
#pragma unroll
            for (int mt = 0; mt < 4; mt++) {
                unsigned ad = uB + (unsigned)((wm*64 + mt*16)*80) + kB + laneA;
                unsigned ah[4], al[4];
                ldsm4(ah, ad);
                ldsm4(al, ad + PSTRIDE*2);
#pragma unroll
                for (int nt = 0; nt < 4; nt++) {
                    mma_bf16(acc[mt][nt], ah, bh[nt]);
                    mma_bf16(acc[mt][nt], al, bh[nt]);
                    if (NPROD == 3) mma_bf16(acc[mt][nt], ah, bl[nt]);
                }
            }
        }
        __syncthreads();
    }

    if (EPI == 1) {
        float sacc[4][2];
#pragma unroll
        for (int mt = 0; mt < 4; mt++) { sacc[mt][0] = 0.f; sacc[mt][1] = 0.f; }
#pragma unroll
        for (int nt = 0; nt < 4; nt++) {
            int c = n0 + wn * 32 + nt * 8 + tig * 2;
            int f = c >> 1;
            float bav = bias[f], bbv = rowScale[f], wcv = addSrc[f];
#pragma unroll
            for (int mt = 0; mt < 4; mt++) {
#pragma unroll
                for (int h2 = 0; h2 < 2; h2++) {
                    float v0 = acc[mt][nt][h2*2 + 0] + bav;
                    float v1 = acc[mt][nt][h2*2 + 1] + bbv;
                    float p = tanhf(v0) * (1.f / (1.f + expf(-v1))) * wcv;
                    sacc[mt][h2] += p;
                }
            }
        }
#pragma unroll
        for (int mt = 0; mt < 4; mt++) {
#pragma unroll
            for (int h2 = 0; h2 < 2; h2++) {
                float s = sacc[mt][h2];
                s += __shfl_xor_sync(0xffffffffu, s, 1);
                s += __shfl_xor_sync(0xffffffffu, s, 2);
                if (tig == 0) {
                    int r = m0 + wm * 64 + mt * 16 + g + h2 * 8;
                    if (r < M) atomicAdd(&Cf[r], s);
                }
            }
        }
        return;
    }

#pragma unroll
    for (int mt = 0; mt < 4; mt++) {
#pragma unroll
        for (int nt = 0; nt < 4; nt++) {
            int rA = m0 + wm * 64 + mt * 16 + g;
            int c = n0 + wn * 32 + nt * 8 + tig * 2;
            if (c >= N) continue;
#pragma unroll
            for (int h2 = 0; h2 < 2; h2++) {
                int r = rA + h2 * 8;
                if (r >= M) continue;
                float v0 = acc[mt][nt][h2*2 + 0];
                float v1 = acc[mt][nt][h2*2 + 1];
                size_t idx = (size_t)r * ldc + c;
                if (atomicOut) {
                    atomicAdd(&Cf[idx], v0);
                    atomicAdd(&Cf[idx+1], v1);
                    continue;
                }
                if (rowScale) { float rs = rowScale[r]; v0 *= rs; v1 *= rs; }
                if (addSrc) { v0 += addSrc[idx]; v1 += addSrc[idx+1]; }
                if (bias) { v0 += bias[c]; v1 += bias[c+1]; }
                if (Cf) *(float2*)&Cf[idx] = make_float2(v0, v1);
                if (Chi) {
                    __nv_bfloat162 hv, lv;
                    bf16 h, l;
                    splitbf(v0, h, l); hv.x = h; lv.x = l;
                    splitbf(v1, h, l); hv.y = h; lv.y = l;
                    *(__nv_bfloat162*)&Chi[idx] = hv;
                    *(__nv_bfloat162*)&Clo[idx] = lv;
                }
            }
        }
    }
}

// ---------------- small kernels ---------------------------------------------
__global__ void sa_kernel() {
    __shared__ float qrow[DIM], sc[MCLUS], pr[MCLUS];
    int i = blockIdx.x, c = threadIdx.x;
    qrow[c] = recbf(qkvH, qkvL, (size_t)i * 768 + c);
    __syncthreads();
    if (c < MCLUS) {
        float s = 0.f;
        for (int k = 0; k < DIM; k++)
            s += qrow[k] * recbf(qkvH, qkvL, (size_t)c * 768 + 256 + k);
        sc[c] = s * SCALE;
    }
    __syncthreads();
    float m = -1e30f;
    for (int t = 0; t < MCLUS; t++) m = fmaxf(m, sc[t]);
    if (c < MCLUS) pr[c] = expf(sc[c] - m);
    __syncthreads();
    float sum = 0.f;
    for (int t = 0; t < MCLUS; t++) sum += pr[t];
    float o = 0.f;
    for (int t = 0; t < MCLUS; t++) o += pr[t] * recbf(qkvH, qkvL, (size_t)t * 768 + 512 + c);
    g_osc[i * DIM + c] = o / sum;
}

__global__ void cap_rowsoft() {
    int row = blockIdx.x * 8 + (threadIdx.x >> 5);
    int lane = threadIdx.x & 31;
    size_t base = (size_t)row * 64;
    float v1 = (lane < MCLUS) ? g_Scap[base + lane] : -1e30f;
    float v2 = (lane + 32 < MCLUS) ? g_Scap[base + 32 + lane] : -1e30f;
    float m = fmaxf(v1, v2);
#pragma unroll
    for (int o = 16; o; o >>= 1) m = fmaxf(m, __shfl_xor_sync(0xffffffffu, m, o));
    float e1 = (lane < MCLUS) ? expf((v1 - m) * SCALE) : 0.f;
    float e2 = (lane + 32 < MCLUS) ? expf((v2 - m) * SCALE) : 0.f;
    float s = e1 + e2;
#pragma unroll
    for (int o = 16; o; o >>= 1) s += __shfl_xor_sync(0xffffffffu, s, o);
    float inv = 1.f / s;
    bf16 h, l;
    splitbf(e1 * inv, h, l); PH[base + lane] = h; PL[base + lane] = l;
    splitbf(e2 * inv, h, l); PH[base + 32 + lane] = h; PL[base + 32 + lane] = l;
}

__global__ void colmax_part() {
    int col = threadIdx.x & 63, rq = threadIdx.x >> 6;
    float m = -1e30f;
    int r0 = blockIdx.x * 1024;
    for (int r = r0 + rq; r < r0 + 1024; r += 4) m = fmaxf(m, g_Scac[(size_t)r * 64 + col]);
    __shared__ float sm[256];
    sm[threadIdx.x] = m;
    __syncthreads();
    if (rq == 0)
        g_pmax[blockIdx.x * 64 + col] =
            fmaxf(fmaxf(sm[col], sm[64+col]), fmaxf(sm[128+col], sm[192+col]));
}
__global__ void colmax_comb() {
    int col = threadIdx.x;
    float m = -1e30f;
    for (int b = 0; b < 64; b++) m = fmaxf(m, g_pmax[b * 64 + col]);
    g_cmax[col] = m;
}
__global__ void cac_exp() {
    int col = threadIdx.x & 63, rq = threadIdx.x >> 6;
    float mx = g_cmax[col];
    float s = 0.f;
    int r0 = blockIdx.x * 1024;
    for (int r = r0 + rq; r < r0 + 1024; r += 4) {
        float v = g_Scac[(size_t)r * 64 + col];
        float e = (col < MCLUS) ? expf((v - mx) * SCALE) : 0.f;
        bf16 h, l; splitbf(e, h, l);
        EH[(size_t)r * 64 + col] = h; EL[(size_t)r * 64 + col] = l;
        s += e;
    }
    __shared__ float sm[256];
    sm[threadIdx.x] = s;
    __syncthreads();
    if (rq == 0 && col < MCLUS)
        atomicAdd(&g_clsum[col], sm[col] + sm[64+col] + sm[128+col] + sm[192+col]);
}
__global__ void cac_div() {
    int i = blockIdx.x, c = threadIdx.x;
    g_occ[i * DIM + c] /= g_clsum[i];
}

// R13 tree-reduction linprep (reverted from R14 shuffle version)
__global__ void linprep_kernel(const float* __restrict__ scale_linear) {
    int i = blockIdx.x, c = threadIdx.x;
    size_t tok = (size_t)(MCLUS + i) * 768;
    float sp = logf(1.f + expf(scale_linear[c]));
    float q = recbf(qkvH, qkvL, tok + c);
    float k = recbf(qkvH, qkvL, tok + 256 + c);
    float tq = (fmaxf(q, 0.f) + 1e-6f) / sp;
    float tk = (fmaxf(k, 0.f) + 1e-6f) / sp;
    float uq = tq*tq*tq, uk = tk*tk*tk;
    __shared__ float4 red[256];
    red[c] = make_float4(tq*tq, uq*uq, tk*tk, uk*uk);
    __syncthreads();
    for (int s = 128; s > 0; s >>= 1) {
        if (c < s) {
            float4 a = red[c], b = red[c + s];
            red[c] = make_float4(a.x+b.x, a.y+b.y, a.z+b.z, a.w+b.w);
        }
        __syncthreads();
    }
    float4 t = red[0];
    float vq = uq * sqrtf(t.x) / sqrtf(t.y);
    float vk = uk * sqrtf(t.z) / sqrtf(t.w);
    size_t o = (size_t)i * DIM + c;
    bf16 h, l;
    splitbf(vq, h, l); qlH[o] = h; qlL[o] = l;
    splitbf(vk, h, l); klH[o] = h; klL[o] = l;
}

__global__ void klsum_kernel() {
    int c = threadIdx.x;
    int r0 = blockIdx.x * (NPATH / 256);
    float s = 0.f;
    for (int r = r0; r < r0 + NPATH / 256; r++)
        s += recbf(klH, klL, (size_t)r * DIM + c);
    atomicAdd(&g_klsum[c], s);
}
__global__ void zfac_kernel() {
    int warp = threadIdx.x >> 5, lane = threadIdx.x & 31;
    int row = blockIdx.x * 8 + warp;
    float s = 0.f;
    for (int cc = lane; cc < DIM; cc += 32)
        s += recbf(qlH, qlL, (size_t)row * DIM + cc) * g_klsum[cc];
    for (int o = 16; o; o >>= 1) s += __shfl_down_sync(0xffffffffu, s, o);
    if (!lane) g_zfac[row] = 1.f / (s + 1e-6f);
}

__global__ void conv_kernel(const float* __restrict__ dwc_w,
                            const float* __restrict__ dwc_b) {
    int d = threadIdx.x;
    int b = blockIdx.x;
    int w0 = (b >> 5) * 4;
    int h0 = (b & 31) * 8;
    float wt[25];
#pragma unroll
    for (int i = 0; i < 25; i++) wt[i] = dwc_w[d * 25 + i];
    float bias = dwc_b[d];
    float acc[4][8];
#pragma unroll
    for (int ow = 0; ow < 4; ow++)
#pragma unroll
        for (int oh = 0; oh < 8; oh++) acc[ow][oh] = bias;

#pragma unroll
    for (int dwa = 0; dwa < 8; dwa++) {
        int wa = w0 + dwa - 2;
        if ((unsigned)wa >= 256u) continue;
#pragma unroll
        for (int dhb = 0; dhb < 12; dhb++) {
            int hb = h0 + dhb - 2;
            if ((unsigned)hb >= 256u) continue;
            float val = recbf(qkvH, qkvL, (size_t)(MCLUS + wa * 256 + hb) * 768 + 512 + d);
#pragma unroll
            for (int ow = 0; ow < 4; ow++) {
                int a = dwa - ow;
                if (a < 0 || a > 4) continue;
#pragma unroll
                for (int oh = 0; oh < 8; oh++) {
                    int bo = dhb - oh;
                    if (bo < 0 || bo > 4) continue;
                    acc[ow][oh] += val * wt[a * 5 + bo];
                }
            }
        }
    }
#pragma unroll
    for (int ow = 0; ow < 4; ow++)
#pragma unroll
        for (int oh = 0; oh < 8; oh++)
            g_spin[(size_t)((w0 + ow) * 256 + h0 + oh) * DIM + d] = acc[ow][oh];
}

__global__ void gated_kernel(const float* __restrict__ T, int nrows,
                             const float* __restrict__ Wa, const float* __restrict__ ba,
                             const float* __restrict__ Wb, const float* __restrict__ bb,
                             const float* __restrict__ Wc,
                             float* __restrict__ Aout)
{
    __shared__ float ts[16 * DIM];
    int c = threadIdx.x;
    int row0 = blockIdx.x * 16;
#pragma unroll
    for (int r = 0; r < 16; r++)
        ts[r * DIM + c] = (row0 + r < nrows) ? T[(size_t)(row0 + r) * DIM + c] : 0.f;
    __syncthreads();
    float aa[16], gg[16];
    float bav = ba[c], bbv = bb[c];
#pragma unroll
    for (int r = 0; r < 16; r++) { aa[r] = bav; gg[r] = bbv; }
    for (int k = 0; k < DIM; k++) {
        float wa = Wa[k * DIM + c];
        float wb = Wb[k * DIM + c];
#pragma unroll
        for (int r = 0; r < 16; r++) {
            float t = ts[r * DIM + k];
            aa[r] += t * wa; gg[r] += t * wb;
        }
    }
    float wcv = Wc[c];
    __syncthreads();
#pragma unroll
    for (int r = 0; r < 16; r++) {
        float a = tanhf(aa[r]);
        float g2 = 1.f / (1.f + expf(-gg[r]));
        ts[r * DIM + c] = a * g2 * wcv;
    }
    __syncthreads();
    int wid = c >> 5, lane = c & 31;
    for (int r = wid; r < 16; r += 8) {
        float s = 0.f;
        for (int cc = lane; cc < DIM; cc += 32) s += ts[r * DIM + cc];
#pragma unroll
        for (int o = 16; o; o >>= 1) s += __shfl_down_sync(0xffffffffu, s, o);
        if (!lane && row0 + r < nrows) Aout[row0 + r] = s;
    }
}

__global__ void fmax_kernel(const float* __restrict__ A, int n, int slot) {
    __shared__ float red[256];
    int t = threadIdx.x;
    float m = -1e30f;
    for (int r = t; r < n; r += 256) m = fmaxf(m, A[r]);
    red[t] = m;
    __syncthreads();
    for (int s = 128; s > 0; s >>= 1) {
        if (t < s) red[t] = fmaxf(red[t], red[t + s]);
        __syncthreads();
    }
    if (!t) g_fmax[slot] = red[0];
}

// fused big-n partial max: blockIdx.y selects array (0=Acp, 1=Asp)
__global__ void fmax_part2() {
    const float* A = blockIdx.y ? g_Asp : g_Acp;
    int i = blockIdx.x * 256 + threadIdx.x;
    float m = A[i];
    int lane = threadIdx.x & 31, warp = threadIdx.x >> 5;
#pragma unroll
    for (int o = 16; o; o >>= 1) m = fmaxf(m, __shfl_xor_sync(0xffffffffu, m, o));
    __shared__ float wred[8];
    if (lane == 0) wred[warp] = m;
    __syncthreads();
    if (threadIdx.x == 0) {
        float mm = wred[0];
#pragma unroll
        for (int wq = 1; wq < 8; wq++) mm = fmaxf(mm, wred[wq]);
        g_fpart[blockIdx.y * 256 + blockIdx.x] = mm;
    }
}
// fused combine: block 0 -> slot1 (cross), block 1 -> slot3 (self)
__global__ void fmax_comb2() {
    int pslot = blockIdx.x;
    int slot = pslot ? 3 : 1;
    int t = threadIdx.x;
    float m = g_fpart[pslot * 256 + t];
    int lane = t & 31, warp = t >> 5;
#pragma unroll
    for (int o = 16; o; o >>= 1) m = fmaxf(m, __shfl_xor_sync(0xffffffffu, m, o));
    __shared__ float wred[8];
    if (lane == 0) wred[warp] = m;
    __syncthreads();
    if (t == 0) {
        float mm = wred[0];
#pragma unroll
        for (int wq = 1; wq < 8; wq++) mm = fmaxf(mm, wred[wq]);
        g_fmax[slot] = mm;
    }
}

__global__ void wsum_kernel(const float* __restrict__ A, const float* __restrict__ X,
                            int n, int slot, int rpb) {
    __shared__ float se[256];
    int c = threadIdx.x;
    int start = blockIdx.x * rpb;
    int end = min(n, start + rpb);
    float mx = g_fmax[slot];
    float h = 0.f, lpart = 0.f;
    for (int r0 = start; r0 < end; r0 += 256) {
        int cnt = min(256, end - r0);
        if (c < cnt) se[c] = expf(A[r0 + c] - mx);
        __syncthreads();
        for (int t = 0; t < cnt; t++) h += se[t] * X[(size_t)(r0 + t) * DIM + c];
        if (c == 0) for (int t = 0; t < cnt; t++) lpart += se[t];
        __syncthreads();
    }
    atomicAdd(&g_fh[slot * DIM + c], h);
    if (c == 0) atomicAdd(&g_fl[slot], lpart);
}

__global__ void wsum_planes(const float* __restrict__ A,
                            const bf16* __restrict__ XH, const bf16* __restrict__ XL,
                            int n, int slot, int rpb, int width, float* __restrict__ outv) {
    __shared__ float se[256];
    int c = threadIdx.x;
    int start = blockIdx.x * rpb;
    int end = min(n, start + rpb);
    float mx = g_fmax[slot];
    float h = 0.f, lpart = 0.f;
    for (int r0 = start; r0 < end; r0 += 256) {
        int cnt = min(256, end - r0);
        if (c < cnt) se[c] = expf(A[r0 + c] - mx);
        __syncthreads();
        if (c < width)
            for (int t = 0; t < cnt; t++) {
                size_t idx = (size_t)(r0 + t) * width + c;
                h += se[t] * (__bfloat162float(XH[idx]) + __bfloat162float(XL[idx]));
            }
        if (c == 0) for (int t = 0; t < cnt; t++) lpart += se[t];
        __syncthreads();
    }
    if (c < width) atomicAdd(&outv[c], h);
    if (c == 0) atomicAdd(&g_fl[slot], lpart);
}

// fused post: block 0 = cross (g_fw @ vc), block 1 = self (g_ft @ Wf + bf*l)
__global__ void post_both(const float* __restrict__ Wf, const float* __restrict__ bfv) {
    int c = threadIdx.x;
    if (blockIdx.x == 0) {
        float s = 0.f;
        for (int j = 0; j < MCLUS; j++)
            s += g_fw[j] * recbf(qkvH, qkvL, (size_t)j * 768 + 512 + c);
        g_fh[1 * DIM + c] = s;
    } else {
        float s0 = 0.f, s1 = 0.f;
#pragma unroll 8
        for (int d = 0; d < 256; d += 2) {
            s0 += g_ft[d] * Wf[d * 256 + c];
            s1 += g_ft[d + 1] * Wf[(d + 1) * 256 + c];
        }
        g_fh[3 * DIM + c] = s0 + s1 + bfv[c] * g_fl[3];
    }
}

__global__ void fuse_final(const float* __restrict__ W1, const float* __restrict__ b1,
                           const float* __restrict__ W2, const float* __restrict__ b2,
                           const float* __restrict__ W3a, const float* __restrict__ b3a,
                           const float* __restrict__ W3b, const float* __restrict__ b3b,
                           float* __restrict__ out)
{
    __shared__ float v0[DIM], v1[DIM], hb2[2 * DIM], ub[DIM];
    int f = blockIdx.x, c = threadIdx.x;
    int s0 = f * 2, s1 = f * 2 + 1;
    v0[c] = g_fh[s0 * DIM + c] / g_fl[s0];
    v1[c] = g_fh[s1 * DIM + c] / g_fl[s1];
    __syncthreads();
    float h1 = b1[c], h2 = b2[c];
    for (int k = 0; k < DIM; k++) {
        h1 += v0[k] * W1[k * DIM + c];
        h2 += v1[k] * W2[k * DIM + c];
    }
    hb2[c] = fmaxf(h1, 0.f);
    hb2[DIM + c] = fmaxf(h2, 0.f);
    __syncthreads();
    float u = b3a[c];
    for (int k = 0; k < 2 * DIM; k++) u += hb2[k] * W3a[k * DIM + c];
    ub[c] = fmaxf(u, 0.f);
    __syncthreads();
    float o = b3b[c];
    for (int k = 0; k < DIM; k++) o += ub[k] * W3b[k * DIM + c];
    out[f * DIM + c] = fmaxf(o, 0.f);
}

// ---------------------------------------------------------------------------
extern "C" void kernel_launch(void* const* d_in, const int* in_sizes, int n_in,
                              void* d_out, int out_size) {
    const float* x   = (const float*)d_in[0];
    const float* Wqkv= (const float*)d_in[1];
    const float* scl = (const float*)d_in[2];
    const float* dwcw= (const float*)d_in[3];
    const float* dwcb= (const float*)d_in[4];
    const float* Wa  = (const float*)d_in[5];
    const float* ba  = (const float*)d_in[6];
    const float* Wb  = (const float*)d_in[7];
    const float* bb  = (const float*)d_in[8];
    const float* Wc  = (const float*)d_in[9];
    const float* W1  = (const float*)d_in[11];
    const float* b1  = (const float*)d_in[12];
    const float* W2  = (const float*)d_in[13];
    const float* b2  = (const float*)d_in[14];
    const float* W3a = (const float*)d_in[15];
    const float* b3a = (const float*)d_in[16];
    const float* W3b = (const float*)d_in[17];
    const float* b3b = (const float*)d_in[18];
    const float* Wf  = (const float*)d_in[19];
    const float* bf  = (const float*)d_in[20];
    float* out = (float*)d_out;

    cudaFuncSetAttribute(bf16gemm<3,0>, cudaFuncAttributeMaxDynamicSharedMemorySize, 81920);
    cudaFuncSetAttribute(bf16gemm<2,0>, cudaFuncAttributeMaxDynamicSharedMemorySize, 81920);
    cudaFuncSetAttribute(bf16gemm<2,1>, cudaFuncAttributeMaxDynamicSharedMemorySize, 81920);
    const int SM = 81920;

#define SYM(p, s) float* p; cudaGetSymbolAddress((void**)&p, s)
    SYM(p_kv, g_kv);
    SYM(p_spin, g_spin); SYM(p_zfac, g_zfac);
    SYM(p_occ, g_occ); SYM(p_osc, g_osc);
    SYM(p_Acp, g_Acp); SYM(p_Asp, g_Asp); SYM(p_Acc, g_Acc); SYM(p_Asc, g_Asc);
    SYM(p_Scap, g_Scap); SYM(p_Scac, g_Scac);
    SYM(p_fw, g_fw); SYM(p_ft, g_ft);
    SYM(p_bfa2, g_bfa2); SYM(p_bfb2, g_bfb2);
#define BSYM(p, s) bf16* p; cudaGetSymbolAddress((void**)&p, s)
    BSYM(b_qkvH, qkvH); BSYM(b_qkvL, qkvL); BSYM(b_xH, xH); BSYM(b_xL, xL);
    BSYM(b_WqT_H, WqkvT_H); BSYM(b_WqT_L, WqkvT_L);
    BSYM(b_vcabT_H, vcabT_H); BSYM(b_vcabT_L, vcabT_L);
    BSYM(b_WfabT_H, WfabT_H); BSYM(b_WfabT_L, WfabT_L);
    BSYM(b_kvT_H, kvT_H); BSYM(b_kvT_L, kvT_L);
    BSYM(b_qlH, qlH); BSYM(b_qlL, qlL); BSYM(b_klH, klH); BSYM(b_klL, klL);
    BSYM(b_PH, PH); BSYM(b_PL, PL); BSYM(b_EH, EH); BSYM(b_EL, EL);
    BSYM(b_spinH, spinH); BSYM(b_spinL, spinL);

    const bf16* vpH = b_qkvH + (size_t)MCLUS * 768 + 512;
    const bf16* vpL = b_qkvL + (size_t)MCLUS * 768 + 512;

    // launches 1-3, qkv GEMM at #4 (ncu capture slot)
    init_kernel<<<64, 256>>>();
    cvt_planar<<<(NTOK * 256 / 4 + 255) / 256, 256>>>(x, b_xH, b_xL, NTOK * 256);
    transpose_cvt<<<dim3(8, 24), dim3(32, 8)>>>(Wqkv, 768, 256, 768, 256, b_WqT_H, b_WqT_L, 1, 0);

    // #4: qkv = x @ Wqkv -> planes only
    bf16gemm<3,0><<<dim3(6, 513), 256, SM>>>(b_xH, b_xL, 256, 0, b_WqT_H, b_WqT_L, 256, 0,
        nullptr, b_qkvH, b_qkvL, 768, NTOK, 768, 256, nullptr, nullptr, nullptr, 0, 768);

    make_wfab<<<256, 256>>>(Wf, Wa, Wb);
    make_bias2<<<1, 256>>>(bf, Wa, ba, Wb, bb);
    sa_kernel<<<MCLUS, 256>>>();
    make_vcab<<<256, 64>>>(Wa, Wb);

    // cap: S = qp @ kc^T (2-prod), row softmax -> P planes
    bf16gemm<2,0><<<dim3(1, 512), 256, SM>>>(b_qkvH + (size_t)MCLUS * 768, b_qkvL + (size_t)MCLUS * 768, 768, 0,
        b_qkvH + 256, b_qkvL + 256, 768, 0, p_Scap, nullptr, nullptr, 64,
        NPATH, 64, 256, nullptr, nullptr, nullptr, 0, MCLUS);
    cap_rowsoft<<<NPATH / 8, 256>>>();

    // cac: S2 = kp @ qc^T (2-prod), col softmax, occ = E^T @ vp / l
    bf16gemm<2,0><<<dim3(1, 512), 256, SM>>>(b_qkvH + (size_t)MCLUS * 768 + 256, b_qkvL + (size_t)MCLUS * 768 + 256, 768, 0,
        b_qkvH, b_qkvL, 768, 0, p_Scac, nullptr, nullptr, 64,
        NPATH, 64, 256, nullptr, nullptr, nullptr, 0, MCLUS);
    colmax_part<<<64, 256>>>();
    colmax_comb<<<1, 64>>>();
    cac_exp<<<64, 256>>>();
    bf16gemm<3,0><<<dim3(2, 1, 32), 256, SM>>>(b_EH, b_EL, 64, 1, vpH, vpL, 768, 1,
        p_occ, nullptr, nullptr, 256, MCLUS, 256, 2048, nullptr, nullptr, nullptr, 1, 256);
    cac_div<<<MCLUS, 256>>>();

    // linear attention
    linprep_kernel<<<NPATH, 256>>>(scl);
    klsum_kernel<<<256, 256>>>();
    zfac_kernel<<<NPATH / 8, 256>>>();
    bf16gemm<3,0><<<dim3(2, 2, 32), 256, SM>>>(b_klH, b_klL, 256, 1, vpH, vpL, 768, 1,
        p_kv, nullptr, nullptr, 256, 256, 256, 2048, nullptr, nullptr, nullptr, 1, 256);
    transpose_cvt<<<dim3(8, 8), dim3(32, 8)>>>(p_kv, 256, 256, 256, 256, b_kvT_H, b_kvT_L, 1, 0);

    conv_kernel<<<2048, 256>>>(dwcw, dwcb);
    // spin = zfac * (ql @ kv) + fm  (planes only)
    bf16gemm<3,0><<<dim3(2, 512), 256, SM>>>(b_qlH, b_qlL, 256, 0, b_kvT_H, b_kvT_L, 256, 0,
        nullptr, b_spinH, b_spinL, 256, NPATH, 256, 256, nullptr, p_zfac, p_spin, 0, 256);

    // small gated scorers (fp32)
    gated_kernel<<<4, 256>>>(p_occ, MCLUS, Wa, ba, Wb, bb, Wc, p_Acc);
    gated_kernel<<<4, 256>>>(p_osc, MCLUS, Wa, ba, Wb, bb, Wc, p_Asc);

    // fused gated cross/self
    bf16gemm<2,1><<<dim3(4, 512), 256, SM>>>(b_PH, b_PL, 64, 0, b_vcabT_H, b_vcabT_L, 64, 0,
        p_Acp, nullptr, nullptr, 0, NPATH, 512, 64, ba, bb, Wc, 0, 512);
    bf16gemm<2,1><<<dim3(4, 512), 256, SM>>>(b_spinH, b_spinL, 256, 0, b_WfabT_H, b_WfabT_L, 256, 0,
        p_Asp, nullptr, nullptr, 0, NPATH, 512, 256, p_bfa2, p_bfb2, Wc, 0, 512);

    // fusion pooling
    fmax_kernel<<<1, 256>>>(p_Acc, MCLUS, 0);
    fmax_kernel<<<1, 256>>>(p_Asc, MCLUS, 2);
    fmax_part2<<<dim3(256, 2), 256>>>();
    fmax_comb2<<<2, 256>>>();
    wsum_kernel<<<1, 256>>>(p_Acc, p_occ, MCLUS, 0, MCLUS);
    wsum_kernel<<<1, 256>>>(p_Asc, p_osc, MCLUS, 2, MCLUS);
    wsum_planes<<<256, 256>>>(p_Acp, b_PH, b_PL, NPATH, 1, 256, 64, p_fw);
    wsum_planes<<<256, 256>>>(p_Asp, b_spinH, b_spinL, NPATH, 3, 256, 256, p_ft);
    post_both<<<2, 256>>>(Wf, bf);

    fuse_final<<<2, 256>>>(W1, b1, W2, b2, W3a, b3a, W3b, b3b, out);
}

// round 16
// speedup vs baseline: 1.4866x; 1.0207x over previous
#include <cuda_runtime.h>
#include <cuda_bf16.h>
#include <math.h>
#include <stdint.h>

#define NTOK   65586
#define MCLUS  50
#define NPATH  65536
#define DIM    256
#define SCALE  0.0625f

typedef __nv_bfloat16 bf16;

// ---------------- fp32 scratch ----------------------------------------------
__device__ float g_osc[MCLUS * DIM];
__device__ float g_occ[MCLUS * DIM];
__device__ float g_klsum[DIM];
__device__ float g_kv[DIM * DIM];
__device__ float g_zfac[NPATH];
__device__ float g_spin[(size_t)NPATH * DIM];
__device__ float g_Scap[(size_t)NPATH * 64];
__device__ float g_Scac[(size_t)NPATH * 64];
__device__ float g_pmax[64 * 64];
__device__ float g_cmax[64];
__device__ float g_clsum[64];
__device__ float g_Acp[NPATH];
__device__ float g_Asp[NPATH];
__device__ float g_Acc[MCLUS];
__device__ float g_Asc[MCLUS];
__device__ float g_fpart[2 * 256];
__device__ float g_fmax[4];
__device__ float g_fl[4];
__device__ float g_fh[4 * DIM];
__device__ float g_fw[64];
__device__ float g_ft[DIM];
__device__ float g_bfa2[DIM];
__device__ float g_bfb2[DIM];

// ---------------- bf16 hi/lo planes -----------------------------------------
__device__ __align__(16) bf16 qkvH[(size_t)NTOK * 768], qkvL[(size_t)NTOK * 768];
__device__ __align__(16) bf16 xH[(size_t)NTOK * 256],  xL[(size_t)NTOK * 256];
__device__ __align__(16) bf16 WqkvT_H[768 * 256], WqkvT_L[768 * 256];
__device__ __align__(16) bf16 vcabT_H[512 * 64], vcabT_L[512 * 64];
__device__ __align__(16) bf16 WfabT_H[(size_t)512 * 256], WfabT_L[(size_t)512 * 256];
__device__ __align__(16) bf16 kvT_H[256 * 256], kvT_L[256 * 256];
__device__ __align__(16) bf16 qlH[(size_t)NPATH * 256], qlL[(size_t)NPATH * 256];
__device__ __align__(16) bf16 klH[(size_t)NPATH * 256], klL[(size_t)NPATH * 256];
__device__ __align__(16) bf16 PH[(size_t)NPATH * 64],  PL[(size_t)NPATH * 64];
__device__ __align__(16) bf16 EH[(size_t)NPATH * 64],  EL[(size_t)NPATH * 64];
__device__ __align__(16) bf16 spinH[(size_t)NPATH * 256], spinL[(size_t)NPATH * 256];

__device__ __forceinline__ void splitbf(float v, bf16& h, bf16& l) {
    h = __float2bfloat16(v);
    l = __float2bfloat16(v - __bfloat162float(h));
}
__device__ __forceinline__ float recbf(const bf16* H, const bf16* L, size_t i) {
    return __bfloat162float(H[i]) + __bfloat162float(L[i]);
}

__global__ void init_kernel() {
    int t = blockIdx.x * 256 + threadIdx.x;
    int nthr = gridDim.x * 256;
    for (int i = t; i < NPATH; i += nthr) { g_Acp[i] = 0.f; g_Asp[i] = 0.f; }
    if (blockIdx.x == 0) {
        int c = threadIdx.x;
        for (int i = c; i < DIM * DIM; i += 256) g_kv[i] = 0.f;
        for (int i = c; i < MCLUS * DIM; i += 256) g_occ[i] = 0.f;
        if (c < DIM) { g_klsum[c] = 0.f; g_ft[c] = 0.f; }
        if (c < 64) { g_clsum[c] = 0.f; g_fw[c] = 0.f; }
        if (c < 4) g_fl[c] = 0.f;
        for (int i = c; i < 4 * DIM; i += 256) g_fh[i] = 0.f;
    }
}

__global__ void cvt_planar(const float* __restrict__ src, bf16* __restrict__ h,
                           bf16* __restrict__ l, int n) {
    int i = (blockIdx.x * 256 + threadIdx.x) * 4;
    if (i >= n) return;
    float4 v = *(const float4*)(src + i);
    bf16 a, b;
    splitbf(v.x, a, b); h[i+0]=a; l[i+0]=b;
    splitbf(v.y, a, b); h[i+1]=a; l[i+1]=b;
    splitbf(v.z, a, b); h[i+2]=a; l[i+2]=b;
    splitbf(v.w, a, b); h[i+3]=a; l[i+3]=b;
}

__global__ void transpose_cvt(const float* __restrict__ src, int ldsrc,
                              int R, int C, int Rpad,
                              bf16* __restrict__ dH, bf16* __restrict__ dL,
                              int rowMul, int rowOff) {
    __shared__ float t[32][33];
    int r0 = blockIdx.x * 32, c0 = blockIdx.y * 32;
    int tx = threadIdx.x, ty = threadIdx.y;
    for (int i = ty; i < 32; i += 8) {
        int r = r0 + i, c = c0 + tx;
        t[i][tx] = (r < R && c < C) ? src[(size_t)r * ldsrc + c] : 0.f;
    }
    __syncthreads();
    for (int i = ty; i < 32; i += 8) {
        int c = c0 + i, r = r0 + tx;
        if (c < C && r < Rpad) {
            bf16 h, l; splitbf(t[tx][i], h, l);
            size_t o = (size_t)(c * rowMul + rowOff) * Rpad + r;
            dH[o] = h; dL[o] = l;
        }
    }
}

__global__ void make_wfab(const float* __restrict__ Wf,
                          const float* __restrict__ Wa, const float* __restrict__ Wb) {
    __shared__ float wrow[256];
    int c = blockIdx.x, f = threadIdx.x;
    wrow[f] = Wf[c * 256 + f];
    __syncthreads();
    float sa0 = 0.f, sa1 = 0.f, sb0 = 0.f, sb1 = 0.f;
#pragma unroll 8
    for (int d = 0; d < 256; d += 2) {
        float w0 = wrow[d], w1 = wrow[d + 1];
        sa0 += w0 * Wa[d * 256 + f];
        sa1 += w1 * Wa[(d + 1) * 256 + f];
        sb0 += w0 * Wb[d * 256 + f];
        sb1 += w1 * Wb[(d + 1) * 256 + f];
    }
    bf16 h, l;
    splitbf(sa0 + sa1, h, l); WfabT_H[(size_t)(2*f)*256 + c] = h;   WfabT_L[(size_t)(2*f)*256 + c] = l;
    splitbf(sb0 + sb1, h, l); WfabT_H[(size_t)(2*f+1)*256 + c] = h; WfabT_L[(size_t)(2*f+1)*256 + c] = l;
}

__global__ void make_bias2(const float* __restrict__ bfv,
                           const float* __restrict__ Wa, const float* __restrict__ ba,
                           const float* __restrict__ Wb, const float* __restrict__ bb) {
    int f = threadIdx.x;
    float sa0 = ba[f], sa1 = 0.f, sb0 = bb[f], sb1 = 0.f;
#pragma unroll 8
    for (int d = 0; d < 256; d += 2) {
        float v0 = bfv[d], v1 = bfv[d + 1];
        sa0 += v0 * Wa[d * 256 + f];
        sa1 += v1 * Wa[(d + 1) * 256 + f];
        sb0 += v0 * Wb[d * 256 + f];
        sb1 += v1 * Wb[(d + 1) * 256 + f];
    }
    g_bfa2[f] = sa0 + sa1; g_bfb2[f] = sb0 + sb1;
}

__global__ void make_vcab(const float* __restrict__ Wa, const float* __restrict__ Wb) {
    int f = blockIdx.x, j = threadIdx.x;
    float sa0 = 0.f, sa1 = 0.f, sb0 = 0.f, sb1 = 0.f;
    if (j < MCLUS) {
#pragma unroll 8
        for (int c = 0; c < 256; c += 2) {
            float v0 = recbf(qkvH, qkvL, (size_t)j * 768 + 512 + c);
            float v1 = recbf(qkvH, qkvL, (size_t)j * 768 + 512 + c + 1);
            sa0 += v0 * Wa[c * 256 + f];
            sa1 += v1 * Wa[(c + 1) * 256 + f];
            sb0 += v0 * Wb[c * 256 + f];
            sb1 += v1 * Wb[(c + 1) * 256 + f];
        }
    }
    bf16 h, l;
    splitbf(sa0 + sa1, h, l); vcabT_H[(2*f)*64 + j] = h;   vcabT_L[(2*f)*64 + j] = l;
    splitbf(sb0 + sb1, h, l); vcabT_H[(2*f+1)*64 + j] = h; vcabT_L[(2*f+1)*64 + j] = l;
}

// ============================================================================
// bf16 planar GEMM. EPI=0: normal. EPI=1: fused gated scorer.
// MMA order: per mt, three nt-sweeps (hh, lh, hl) — consecutive MMAs hit
// different accumulators (ILP 4) while per-acc order is unchanged.
// ============================================================================
#define PSTRIDE 5120
#define STSTRIDE 20480

__device__ __forceinline__ void cp16(unsigned dst, const void* src, bool valid) {
    int sz = valid ? 16 : 0;
    asm volatile("cp.async.cg.shared.global [%0], [%1], 16, %2;\n"
                 :: "r"(dst), "l"(src), "r"(sz));
}
__device__ __forceinline__ void mma_bf16(float* c, const unsigned* a, const unsigned* b) {
    asm volatile(
        "mma.sync.aligned.m16n8k16.row.col.f32.bf16.bf16.f32 "
        "{%0,%1,%2,%3},{%4,%5,%6,%7},{%8,%9},{%0,%1,%2,%3};\n"
        : "+f"(c[0]), "+f"(c[1]), "+f"(c[2]), "+f"(c[3])
        : "r"(a[0]), "r"(a[1]), "r"(a[2]), "r"(a[3]), "r"(b[0]), "r"(b[1]));
}
__device__ __forceinline__ void ldsm4(unsigned* r, unsigned addr) {
    asm volatile("ldmatrix.sync.aligned.m8n8.x4.shared.b16 {%0,%1,%2,%3}, [%4];"
        : "=r"(r[0]), "=r"(r[1]), "=r"(r[2]), "=r"(r[3]) : "r"(addr));
}

__device__ __forceinline__ void stage_tile(
    bf16* sb,
    const bf16* __restrict__ Ahi, const bf16* __restrict__ Alo, int lda, int transA,
    const bf16* __restrict__ Bhi, const bf16* __restrict__ Blo, int ldb, int transB,
    int m0, int n0, int k0, int M, int nBound, int tid)
{
    int r = tid & 127;
    int kh = (tid >> 7) << 4;
    if (!transB) {
        bool v = (n0 + r) < nBound;
        const bf16* gh = v ? (Bhi + (size_t)(n0 + r) * ldb + k0 + kh) : Bhi;
        const bf16* gl = v ? (Blo + (size_t)(n0 + r) * ldb + k0 + kh) : Blo;
        unsigned sh = (unsigned)__cvta_generic_to_shared(sb + 2*PSTRIDE + r*40 + kh);
        unsigned sl = (unsigned)__cvta_generic_to_shared(sb + 3*PSTRIDE + r*40 + kh);
        cp16(sh, gh, v); cp16(sh + 16, gh + 8, v);
        cp16(sl, gl, v); cp16(sl + 16, gl + 8, v);
    } else {
        int n8 = (tid & 15) * 8;
        int kq = tid >> 4;
        bf16 z = __float2bfloat16(0.f);
#pragma unroll
        for (int e = 0; e < 2; e++) {
            int kk = kq + (e << 4);
            const bf16* gh = Bhi + (size_t)(k0 + kk) * ldb + n0 + n8;
            const bf16* gl = Blo + (size_t)(k0 + kk) * ldb + n0 + n8;
            if (n0 + n8 + 7 < nBound) {
                uint4 vh = *(const uint4*)gh;
                uint4 vl = *(const uint4*)gl;
                const bf16* eh = (const bf16*)&vh;
                const bf16* el = (const bf16*)&vl;
#pragma unroll
                for (int j = 0; j < 8; j++) {
                    sb[2*PSTRIDE + (n8+j)*40 + kk] = eh[j];
                    sb[3*PSTRIDE + (n8+j)*40 + kk] = el[j];
                }
            } else {
#pragma unroll
                for (int j = 0; j < 8; j++) {
                    bool ok = (n0 + n8 + j) < nBound;
                    sb[2*PSTRIDE + (n8+j)*40 + kk] = ok ? gh[j] : z;
                    sb[3*PSTRIDE + (n8+j)*40 + kk] = ok ? gl[j] : z;
                }
            }
        }
    }
    if (!transA) {
        bool v = (m0 + r) < M;
        const bf16* gh = v ? (Ahi + (size_t)(m0 + r) * lda + k0 + kh) : Ahi;
        const bf16* gl = v ? (Alo + (size_t)(m0 + r) * lda + k0 + kh) : Alo;
        unsigned sh = (unsigned)__cvta_generic_to_shared(sb + r*40 + kh);
        unsigned sl = (unsigned)__cvta_generic_to_shared(sb + PSTRIDE + r*40 + kh);
        cp16(sh, gh, v); cp16(sh + 16, gh + 8, v);
        cp16(sl, gl, v); cp16(sl + 16, gl + 8, v);
    } else {
        int m8 = (tid & 15) * 8;
        int kq = tid >> 4;
        bf16 z = __float2bfloat16(0.f);
#pragma unroll
        for (int e = 0; e < 2; e++) {
            int kk = kq + (e << 4);
            const bf16* gh = Ahi + (size_t)(k0 + kk) * lda + m0 + m8;
            const bf16* gl = Alo + (size_t)(k0 + kk) * lda + m0 + m8;
            if (m0 + m8 + 7 < lda) {
                uint4 vh = *(const uint4*)gh;
                uint4 vl = *(const uint4*)gl;
                const bf16* eh = (const bf16*)&vh;
                const bf16* el = (const bf16*)&vl;
#pragma unroll
                for (int j = 0; j < 8; j++) {
                    sb[(m8+j)*40 + kk] = eh[j];
                    sb[PSTRIDE + (m8+j)*40 + kk] = el[j];
                }
            } else {
#pragma unroll
                for (int j = 0; j < 8; j++) {
                    bool ok = (m0 + m8 + j) < lda;
                    sb[(m8+j)*40 + kk] = ok ? gh[j] : z;
                    sb[PSTRIDE + (m8+j)*40 + kk] = ok ? gl[j] : z;
                }
            }
        }
    }
}

template<int NPROD, int EPI>
__global__ void __launch_bounds__(256, 2) bf16gemm(
    const bf16* __restrict__ Ahi, const bf16* __restrict__ Alo, int lda, int transA,
    const bf16* __restrict__ Bhi, const bf16* __restrict__ Blo, int ldb, int transB,
    float* __restrict__ Cf, bf16* __restrict__ Chi, bf16* __restrict__ Clo, int ldc,
    int M, int N, int kRange,
    const float* __restrict__ bias, const float* __restrict__ rowScale,
    const float* __restrict__ addSrc, int atomicOut, int nBound)
{
    extern __shared__ bf16 smdyn[];
    int tid = threadIdx.x;
    int w = tid >> 5, lane = tid & 31;
    int wm = w >> 2, wn = w & 3;
    int g = lane >> 2, tig = lane & 3;

    int m0 = blockIdx.y * 128;
    int n0 = blockIdx.x * 128;
    int k0beg = blockIdx.z * kRange;
    int nIter = kRange >> 5;

    unsigned uBase = (unsigned)__cvta_generic_to_shared(smdyn);
    unsigned laneA  = (unsigned)((lane & 15) * 80 + (lane >> 4) * 16);
    unsigned laneB4 = (unsigned)((lane & 7) * 80 + ((lane >> 3) & 1) * 16 + ((lane >> 4) & 1) * 640);

    float acc[4][4][4];
#pragma unroll
    for (int i = 0; i < 4; i++)
#pragma unroll
        for (int j = 0; j < 4; j++)
#pragma unroll
            for (int q = 0; q < 4; q++) acc[i][j][q] = 0.f;

    stage_tile(smdyn, Ahi, Alo, lda, transA, Bhi, Blo, ldb, transB,
               m0, n0, k0beg, M, nBound, tid);
    asm volatile("cp.async.commit_group;\n");

    for (int it = 0; it < nIter; it++) {
        if (it + 1 < nIter) {
            stage_tile(smdyn + ((it+1)&1)*STSTRIDE, Ahi, Alo, lda, transA,
                       Bhi, Blo, ldb, transB, m0, n0, k0beg + (it+1)*32, M, nBound, tid);
            asm volatile("cp.async.commit_group;\n");
            asm volatile("cp.async.wait_group 1;\n");
        } else {
            asm volatile("cp.async.wait_group 0;\n");
        }
        __syncthreads();

        unsigned uB = uBase + (unsigned)((it & 1) * STSTRIDE * 2);
#pragma unroll
        for (int ks = 0; ks < 2; ks++) {
            unsigned kB = (unsigned)(ks * 32);
            unsigned bh[4][2], bl[4][2];
#pragma unroll
            for (int ntp = 0; ntp < 2; ntp++) {
                unsigned ad = uB + (unsigned)(2*PSTRIDE*2 + (wn*32 + ntp*16)*80) + kB + laneB4;
                unsigned t4[4];
                ldsm4(t4, ad);
                bh[2*ntp][0] = t4[0]; bh[2*ntp][1] = t4[1];
                bh[2*ntp+1][0] = t4[2]; bh[2*ntp+1][1] = t4[3];
                ldsm4(t4, ad + PSTRIDE*2);
                bl[2*ntp][0] = t4[0]; bl[2*ntp][1] = t4[1];
                bl[2*ntp+1][0] = t4[2]; bl[2*ntp+1][1] = t4[3];
            }
#pragma unroll
            for (int mt = 0; mt < 4; mt++) {
                unsigned ad = uB + (unsigned)((wm*64 + mt*16)*80) + kB + laneA;
                unsigned ah[4], al[4];
                ldsm4(ah, ad);
                ldsm4(al, ad + PSTRIDE*2);
                // interleaved: consecutive MMAs target different accumulators;
                // per-accumulator order (hh, lh, hl) unchanged -> bit-identical
#pragma unroll
                for (int nt = 0; nt < 4; nt++) mma_bf16(acc[mt][nt], ah, bh[nt]);
#pragma unroll
                for (int nt = 0; nt < 4; nt++) mma_bf16(acc[mt][nt], al, bh[nt]);
                if (NPROD == 3) {
#pragma unroll
                    for (int nt = 0; nt < 4; nt++) mma_bf16(acc[mt][nt], ah, bl[nt]);
                }
            }
        }
        __syncthreads();
    }

    if (EPI == 1) {
        float sacc[4][2];
#pragma unroll
        for (int mt = 0; mt < 4; mt++) { sacc[mt][0] = 0.f; sacc[mt][1] = 0.f; }
#pragma unroll
        for (int nt = 0; nt < 4; nt++) {
            int c = n0 + wn * 32 + nt * 8 + tig * 2;
            int f = c >> 1;
            float bav = bias[f], bbv = rowScale[f], wcv = addSrc[f];
#pragma unroll
            for (int mt = 0; mt < 4; mt++) {
#pragma unroll
                for (int h2 = 0; h2 < 2; h2++) {
                    float v0 = acc[mt][nt][h2*2 + 0] + bav;
                    float v1 = acc[mt][nt][h2*2 + 1] + bbv;
                    float p = tanhf(v0) * (1.f / (1.f + expf(-v1))) * wcv;
                    sacc[mt][h2] += p;
                }
            }
        }
#pragma unroll
        for (int mt = 0; mt < 4; mt++) {
#pragma unroll
            for (int h2 = 0; h2 < 2; h2++) {
                float s = sacc[mt][h2];
                s += __shfl_xor_sync(0xffffffffu, s, 1);
                s += __shfl_xor_sync(0xffffffffu, s, 2);
                if (tig == 0) {
                    int r = m0 + wm * 64 + mt * 16 + g + h2 * 8;
                    if (r < M) atomicAdd(&Cf[r], s);
                }
            }
        }
        return;
    }

#pragma unroll
    for (int mt = 0; mt < 4; mt++) {
#pragma unroll
        for (int nt = 0; nt < 4; nt++) {
            int rA = m0 + wm * 64 + mt * 16 + g;
            int c = n0 + wn * 32 + nt * 8 + tig * 2;
            if (c >= N) continue;
#pragma unroll
            for (int h2 = 0; h2 < 2; h2++) {
                int r = rA + h2 * 8;
                if (r >= M) continue;
                float v0 = acc[mt][nt][h2*2 + 0];
                float v1 = acc[mt][nt][h2*2 + 1];
                size_t idx = (size_t)r * ldc + c;
                if (atomicOut) {
                    atomicAdd(&Cf[idx], v0);
                    atomicAdd(&Cf[idx+1], v1);
                    continue;
                }
                if (rowScale) { float rs = rowScale[r]; v0 *= rs; v1 *= rs; }
                if (addSrc) { v0 += addSrc[idx]; v1 += addSrc[idx+1]; }
                if (bias) { v0 += bias[c]; v1 += bias[c+1]; }
                if (Cf) *(float2*)&Cf[idx] = make_float2(v0, v1);
                if (Chi) {
                    __nv_bfloat162 hv, lv;
                    bf16 h, l;
                    splitbf(v0, h, l); hv.x = h; lv.x = l;
                    splitbf(v1, h, l); hv.y = h; lv.y = l;
                    *(__nv_bfloat162*)&Chi[idx] = hv;
                    *(__nv_bfloat162*)&Clo[idx] = lv;
                }
            }
        }
    }
}

// ---------------- small kernels ---------------------------------------------
__global__ void sa_kernel() {
    __shared__ float qrow[DIM], sc[MCLUS], pr[MCLUS];
    int i = blockIdx.x, c = threadIdx.x;
    qrow[c] = recbf(qkvH, qkvL, (size_t)i * 768 + c);
    __syncthreads();
    if (c < MCLUS) {
        float s = 0.f;
        for (int k = 0; k < DIM; k++)
            s += qrow[k] * recbf(qkvH, qkvL, (size_t)c * 768 + 256 + k);
        sc[c] = s * SCALE;
    }
    __syncthreads();
    float m = -1e30f;
    for (int t = 0; t < MCLUS; t++) m = fmaxf(m, sc[t]);
    if (c < MCLUS) pr[c] = expf(sc[c] - m);
    __syncthreads();
    float sum = 0.f;
    for (int t = 0; t < MCLUS; t++) sum += pr[t];
    float o = 0.f;
    for (int t = 0; t < MCLUS; t++) o += pr[t] * recbf(qkvH, qkvL, (size_t)t * 768 + 512 + c);
    g_osc[i * DIM + c] = o / sum;
}

__global__ void cap_rowsoft() {
    int row = blockIdx.x * 8 + (threadIdx.x >> 5);
    int lane = threadIdx.x & 31;
    size_t base = (size_t)row * 64;
    float v1 = (lane < MCLUS) ? g_Scap[base + lane] : -1e30f;
    float v2 = (lane + 32 < MCLUS) ? g_Scap[base + 32 + lane] : -1e30f;
    float m = fmaxf(v1, v2);
#pragma unroll
    for (int o = 16; o; o >>= 1) m = fmaxf(m, __shfl_xor_sync(0xffffffffu, m, o));
    float e1 = (lane < MCLUS) ? expf((v1 - m) * SCALE) : 0.f;
    float e2 = (lane + 32 < MCLUS) ? expf((v2 - m) * SCALE) : 0.f;
    float s = e1 + e2;
#pragma unroll
    for (int o = 16; o; o >>= 1) s += __shfl_xor_sync(0xffffffffu, s, o);
    float inv = 1.f / s;
    bf16 h, l;
    splitbf(e1 * inv, h, l); PH[base + lane] = h; PL[base + lane] = l;
    splitbf(e2 * inv, h, l); PH[base + 32 + lane] = h; PL[base + 32 + lane] = l;
}

__global__ void colmax_part() {
    int col = threadIdx.x & 63, rq = threadIdx.x >> 6;
    float m = -1e30f;
    int r0 = blockIdx.x * 1024;
    for (int r = r0 + rq; r < r0 + 1024; r += 4) m = fmaxf(m, g_Scac[(size_t)r * 64 + col]);
    __shared__ float sm[256];
    sm[threadIdx.x] = m;
    __syncthreads();
    if (rq == 0)
        g_pmax[blockIdx.x * 64 + col] =
            fmaxf(fmaxf(sm[col], sm[64+col]), fmaxf(sm[128+col], sm[192+col]));
}
__global__ void colmax_comb() {
    int col = threadIdx.x;
    float m = -1e30f;
    for (int b = 0; b < 64; b++) m = fmaxf(m, g_pmax[b * 64 + col]);
    g_cmax[col] = m;
}
__global__ void cac_exp() {
    int col = threadIdx.x & 63, rq = threadIdx.x >> 6;
    float mx = g_cmax[col];
    float s = 0.f;
    int r0 = blockIdx.x * 1024;
    for (int r = r0 + rq; r < r0 + 1024; r += 4) {
        float v = g_Scac[(size_t)r * 64 + col];
        float e = (col < MCLUS) ? expf((v - mx) * SCALE) : 0.f;
        bf16 h, l; splitbf(e, h, l);
        EH[(size_t)r * 64 + col] = h; EL[(size_t)r * 64 + col] = l;
        s += e;
    }
    __shared__ float sm[256];
    sm[threadIdx.x] = s;
    __syncthreads();
    if (rq == 0 && col < MCLUS)
        atomicAdd(&g_clsum[col], sm[col] + sm[64+col] + sm[128+col] + sm[192+col]);
}
__global__ void cac_div() {
    int i = blockIdx.x, c = threadIdx.x;
    g_occ[i * DIM + c] /= g_clsum[i];
}

__global__ void linprep_kernel(const float* __restrict__ scale_linear) {
    int i = blockIdx.x, c = threadIdx.x;
    size_t tok = (size_t)(MCLUS + i) * 768;
    float sp = logf(1.f + expf(scale_linear[c]));
    float q = recbf(qkvH, qkvL, tok + c);
    float k = recbf(qkvH, qkvL, tok + 256 + c);
    float tq = (fmaxf(q, 0.f) + 1e-6f) / sp;
    float tk = (fmaxf(k, 0.f) + 1e-6f) / sp;
    float uq = tq*tq*tq, uk = tk*tk*tk;
    __shared__ float4 red[256];
    red[c] = make_float4(tq*tq, uq*uq, tk*tk, uk*uk);
    __syncthreads();
    for (int s = 128; s > 0; s >>= 1) {
        if (c < s) {
            float4 a = red[c], b = red[c + s];
            red[c] = make_float4(a.x+b.x, a.y+b.y, a.z+b.z, a.w+b.w);
        }
        __syncthreads();
    }
    float4 t = red[0];
    float vq = uq * sqrtf(t.x) / sqrtf(t.y);
    float vk = uk * sqrtf(t.z) / sqrtf(t.w);
    size_t o = (size_t)i * DIM + c;
    bf16 h, l;
    splitbf(vq, h, l); qlH[o] = h; qlL[o] = l;
    splitbf(vk, h, l); klH[o] = h; klL[o] = l;
}

__global__ void klsum_kernel() {
    int c = threadIdx.x;
    int r0 = blockIdx.x * (NPATH / 256);
    float s = 0.f;
    for (int r = r0; r < r0 + NPATH / 256; r++)
        s += recbf(klH, klL, (size_t)r * DIM + c);
    atomicAdd(&g_klsum[c], s);
}
__global__ void zfac_kernel() {
    int warp = threadIdx.x >> 5, lane = threadIdx.x & 31;
    int row = blockIdx.x * 8 + warp;
    float s = 0.f;
    for (int cc = lane; cc < DIM; cc += 32)
        s += recbf(qlH, qlL, (size_t)row * DIM + cc) * g_klsum[cc];
    for (int o = 16; o; o >>= 1) s += __shfl_down_sync(0xffffffffu, s, o);
    if (!lane) g_zfac[row] = 1.f / (s + 1e-6f);
}

__global__ void conv_kernel(const float* __restrict__ dwc_w,
                            const float* __restrict__ dwc_b) {
    int d = threadIdx.x;
    int b = blockIdx.x;
    int w0 = (b >> 5) * 4;
    int h0 = (b & 31) * 8;
    float wt[25];
#pragma unroll
    for (int i = 0; i < 25; i++) wt[i] = dwc_w[d * 25 + i];
    float bias = dwc_b[d];
    float acc[4][8];
#pragma unroll
    for (int ow = 0; ow < 4; ow++)
#pragma unroll
        for (int oh = 0; oh < 8; oh++) acc[ow][oh] = bias;

#pragma unroll
    for (int dwa = 0; dwa < 8; dwa++) {
        int wa = w0 + dwa - 2;
        if ((unsigned)wa >= 256u) continue;
#pragma unroll
        for (int dhb = 0; dhb < 12; dhb++) {
            int hb = h0 + dhb - 2;
            if ((unsigned)hb >= 256u) continue;
            float val = recbf(qkvH, qkvL, (size_t)(MCLUS + wa * 256 + hb) * 768 + 512 + d);
#pragma unroll
            for (int ow = 0; ow < 4; ow++) {
                int a = dwa - ow;
                if (a < 0 || a > 4) continue;
#pragma unroll
                for (int oh = 0; oh < 8; oh++) {
                    int bo = dhb - oh;
                    if (bo < 0 || bo > 4) continue;
                    acc[ow][oh] += val * wt[a * 5 + bo];
                }
            }
        }
    }
#pragma unroll
    for (int ow = 0; ow < 4; ow++)
#pragma unroll
        for (int oh = 0; oh < 8; oh++)
            g_spin[(size_t)((w0 + ow) * 256 + h0 + oh) * DIM + d] = acc[ow][oh];
}

// merged small gated scorers: blocks 0-3 occ->Acc, 4-7 osc->Asc
__global__ void gated_pair(const float* __restrict__ Wa, const float* __restrict__ ba,
                           const float* __restrict__ Wb, const float* __restrict__ bb,
                           const float* __restrict__ Wc)
{
    const float* T = (blockIdx.x < 4) ? g_occ : g_osc;
    float* Aout = (blockIdx.x < 4) ? g_Acc : g_Asc;
    int row0 = (blockIdx.x & 3) * 16;
    __shared__ float ts[16 * DIM];
    int c = threadIdx.x;
#pragma unroll
    for (int r = 0; r < 16; r++)
        ts[r * DIM + c] = (row0 + r < MCLUS) ? T[(size_t)(row0 + r) * DIM + c] : 0.f;
    __syncthreads();
    float aa[16], gg[16];
    float bav = ba[c], bbv = bb[c];
#pragma unroll
    for (int r = 0; r < 16; r++) { aa[r] = bav; gg[r] = bbv; }
    for (int k = 0; k < DIM; k++) {
        float wa = Wa[k * DIM + c];
        float wb = Wb[k * DIM + c];
#pragma unroll
        for (int r = 0; r < 16; r++) {
            float t = ts[r * DIM + k];
            aa[r] += t * wa; gg[r] += t * wb;
        }
    }
    float wcv = Wc[c];
    __syncthreads();
#pragma unroll
    for (int r = 0; r < 16; r++) {
        float a = tanhf(aa[r]);
        float g2 = 1.f / (1.f + expf(-gg[r]));
        ts[r * DIM + c] = a * g2 * wcv;
    }
    __syncthreads();
    int wid = c >> 5, lane = c & 31;
    for (int r = wid; r < 16; r += 8) {
        float s = 0.f;
        for (int cc = lane; cc < DIM; cc += 32) s += ts[r * DIM + cc];
#pragma unroll
        for (int o = 16; o; o >>= 1) s += __shfl_down_sync(0xffffffffu, s, o);
        if (!lane && row0 + r < MCLUS) Aout[row0 + r] = s;
    }
}

// merged small fmax: block 0 Acc->slot0, block 1 Asc->slot2
__global__ void fmax_small2() {
    const float* A = blockIdx.x ? g_Asc : g_Acc;
    int slot = blockIdx.x ? 2 : 0;
    __shared__ float red[256];
    int t = threadIdx.x;
    float m = -1e30f;
    for (int r = t; r < MCLUS; r += 256) m = fmaxf(m, A[r]);
    red[t] = m;
    __syncthreads();
    for (int s = 128; s > 0; s >>= 1) {
        if (t < s) red[t] = fmaxf(red[t], red[t + s]);
        __syncthreads();
    }
    if (!t) g_fmax[slot] = red[0];
}

__global__ void fmax_part2() {
    const float* A = blockIdx.y ? g_Asp : g_Acp;
    int i = blockIdx.x * 256 + threadIdx.x;
    float m = A[i];
    int lane = threadIdx.x & 31, warp = threadIdx.x >> 5;
#pragma unroll
    for (int o = 16; o; o >>= 1) m = fmaxf(m, __shfl_xor_sync(0xffffffffu, m, o));
    __shared__ float wred[8];
    if (lane == 0) wred[warp] = m;
    __syncthreads();
    if (threadIdx.x == 0) {
        float mm = wred[0];
#pragma unroll
        for (int wq = 1; wq < 8; wq++) mm = fmaxf(mm, wred[wq]);
        g_fpart[blockIdx.y * 256 + blockIdx.x] = mm;
    }
}
__global__ void fmax_comb2() {
    int pslot = blockIdx.x;
    int slot = pslot ? 3 : 1;
    int t = threadIdx.x;
    float m = g_fpart[pslot * 256 + t];
    int lane = t & 31, warp = t >> 5;
#pragma unroll
    for (int o = 16; o; o >>= 1) m = fmaxf(m, __shfl_xor_sync(0xffffffffu, m, o));
    __shared__ float wred[8];
    if (lane == 0) wred[warp] = m;
    __syncthreads();
    if (t == 0) {
        float mm = wred[0];
#pragma unroll
        for (int wq = 1; wq < 8; wq++) mm = fmaxf(mm, wred[wq]);
        g_fmax[slot] = mm;
    }
}

// merged small wsum: block 0 (Acc,occ,slot0), block 1 (Asc,osc,slot2)
__global__ void wsum_small2() {
    const float* A = blockIdx.x ? g_Asc : g_Acc;
    const float* X = blockIdx.x ? g_osc : g_occ;
    int slot = blockIdx.x ? 2 : 0;
    __shared__ float se[64];
    int c = threadIdx.x;
    float mx = g_fmax[slot];
    if (c < MCLUS) se[c] = expf(A[c] - mx);
    __syncthreads();
    float h = 0.f;
    for (int t = 0; t < MCLUS; t++) h += se[t] * X[(size_t)t * DIM + c];
    g_fh[slot * DIM + c] = h;
    if (c == 0) {
        float lp = 0.f;
        for (int t = 0; t < MCLUS; t++) lp += se[t];
        g_fl[slot] = lp;
    }
}

__global__ void wsum_planes(const float* __restrict__ A,
                            const bf16* __restrict__ XH, const bf16* __restrict__ XL,
                            int n, int slot, int rpb, int width, float* __restrict__ outv) {
    __shared__ float se[256];
    int c = threadIdx.x;
    int start = blockIdx.x * rpb;
    int end = min(n, start + rpb);
    float mx = g_fmax[slot];
    float h = 0.f, lpart = 0.f;
    for (int r0 = start; r0 < end; r0 += 256) {
        int cnt = min(256, end - r0);
        if (c < cnt) se[c] = expf(A[r0 + c] - mx);
        __syncthreads();
        if (c < width)
            for (int t = 0; t < cnt; t++) {
                size_t idx = (size_t)(r0 + t) * width + c;
                h += se[t] * (__bfloat162float(XH[idx]) + __bfloat162float(XL[idx]));
            }
        if (c == 0) for (int t = 0; t < cnt; t++) lpart += se[t];
        __syncthreads();
    }
    if (c < width) atomicAdd(&outv[c], h);
    if (c == 0) atomicAdd(&g_fl[slot], lpart);
}

__global__ void post_both(const float* __restrict__ Wf, const float* __restrict__ bfv) {
    int c = threadIdx.x;
    if (blockIdx.x == 0) {
        float s = 0.f;
        for (int j = 0; j < MCLUS; j++)
            s += g_fw[j] * recbf(qkvH, qkvL, (size_t)j * 768 + 512 + c);
        g_fh[1 * DIM + c] = s;
    } else {
        float s0 = 0.f, s1 = 0.f;
#pragma unroll 8
        for (int d = 0; d < 256; d += 2) {
            s0 += g_ft[d] * Wf[d * 256 + c];
            s1 += g_ft[d + 1] * Wf[(d + 1) * 256 + c];
        }
        g_fh[3 * DIM + c] = s0 + s1 + bfv[c] * g_fl[3];
    }
}

__global__ void fuse_final(const float* __restrict__ W1, const float* __restrict__ b1,
                           const float* __restrict__ W2, const float* __restrict__ b2,
                           const float* __restrict__ W3a, const float* __restrict__ b3a,
                           const float* __restrict__ W3b, const float* __restrict__ b3b,
                           float* __restrict__ out)
{
    __shared__ float v0[DIM], v1[DIM], hb2[2 * DIM], ub[DIM];
    int f = blockIdx.x, c = threadIdx.x;
    int s0 = f * 2, s1 = f * 2 + 1;
    v0[c] = g_fh[s0 * DIM + c] / g_fl[s0];
    v1[c] = g_fh[s1 * DIM + c] / g_fl[s1];
    __syncthreads();
    float h1 = b1[c], h2 = b2[c];
    for (int k = 0; k < DIM; k++) {
        h1 += v0[k] * W1[k * DIM + c];
        h2 += v1[k] * W2[k * DIM + c];
    }
    hb2[c] = fmaxf(h1, 0.f);
    hb2[DIM + c] = fmaxf(h2, 0.f);
    __syncthreads();
    float u = b3a[c];
    for (int k = 0; k < 2 * DIM; k++) u += hb2[k] * W3a[k * DIM + c];
    ub[c] = fmaxf(u, 0.f);
    __syncthreads();
    float o = b3b[c];
    for (int k = 0; k < DIM; k++) o += ub[k] * W3b[k * DIM + c];
    out[f * DIM + c] = fmaxf(o, 0.f);
}

// ---------------------------------------------------------------------------
extern "C" void kernel_launch(void* const* d_in, const int* in_sizes, int n_in,
                              void* d_out, int out_size) {
    const float* x   = (const float*)d_in[0];
    const float* Wqkv= (const float*)d_in[1];
    const float* scl = (const float*)d_in[2];
    const float* dwcw= (const float*)d_in[3];
    const float* dwcb= (const float*)d_in[4];
    const float* Wa  = (const float*)d_in[5];
    const float* ba  = (const float*)d_in[6];
    const float* Wb  = (const float*)d_in[7];
    const float* bb  = (const float*)d_in[8];
    const float* Wc  = (const float*)d_in[9];
    const float* W1  = (const float*)d_in[11];
    const float* b1  = (const float*)d_in[12];
    const float* W2  = (const float*)d_in[13];
    const float* b2  = (const float*)d_in[14];
    const float* W3a = (const float*)d_in[15];
    const float* b3a = (const float*)d_in[16];
    const float* W3b = (const float*)d_in[17];
    const float* b3b = (const float*)d_in[18];
    const float* Wf  = (const float*)d_in[19];
    const float* bf  = (const float*)d_in[20];
    float* out = (float*)d_out;

    cudaFuncSetAttribute(bf16gemm<3,0>, cudaFuncAttributeMaxDynamicSharedMemorySize, 81920);
    cudaFuncSetAttribute(bf16gemm<2,0>, cudaFuncAttributeMaxDynamicSharedMemorySize, 81920);
    cudaFuncSetAttribute(bf16gemm<2,1>, cudaFuncAttributeMaxDynamicSharedMemorySize, 81920);
    const int SM = 81920;

#define SYM(p, s) float* p; cudaGetSymbolAddress((void**)&p, s)
    SYM(p_kv, g_kv);
    SYM(p_spin, g_spin); SYM(p_zfac, g_zfac);
    SYM(p_occ, g_occ); SYM(p_osc, g_osc);
    SYM(p_Acp, g_Acp); SYM(p_Asp, g_Asp);
    SYM(p_Scap, g_Scap); SYM(p_Scac, g_Scac);
    SYM(p_fw, g_fw); SYM(p_ft, g_ft);
    SYM(p_bfa2, g_bfa2); SYM(p_bfb2, g_bfb2);
#define BSYM(p, s) bf16* p; cudaGetSymbolAddress((void**)&p, s)
    BSYM(b_qkvH, qkvH); BSYM(b_qkvL, qkvL); BSYM(b_xH, xH); BSYM(b_xL, xL);
    BSYM(b_WqT_H, WqkvT_H); BSYM(b_WqT_L, WqkvT_L);
    BSYM(b_vcabT_H, vcabT_H); BSYM(b_vcabT_L, vcabT_L);
    BSYM(b_WfabT_H, WfabT_H); BSYM(b_WfabT_L, WfabT_L);
    BSYM(b_kvT_H, kvT_H); BSYM(b_kvT_L, kvT_L);
    BSYM(b_qlH, qlH); BSYM(b_qlL, qlL); BSYM(b_klH, klH); BSYM(b_klL, klL);
    BSYM(b_PH, PH); BSYM(b_PL, PL); BSYM(b_EH, EH); BSYM(b_EL, EL);
    BSYM(b_spinH, spinH); BSYM(b_spinL, spinL);

    const bf16* vpH = b_qkvH + (size_t)MCLUS * 768 + 512;
    const bf16* vpL = b_qkvL + (size_t)MCLUS * 768 + 512;

    // launches 1-3, qkv GEMM at #4 (ncu capture slot)
    init_kernel<<<64, 256>>>();
    cvt_planar<<<(NTOK * 256 / 4 + 255) / 256, 256>>>(x, b_xH, b_xL, NTOK * 256);
    transpose_cvt<<<dim3(8, 24), dim3(32, 8)>>>(Wqkv, 768, 256, 768, 256, b_WqT_H, b_WqT_L, 1, 0);

    // #4: qkv = x @ Wqkv -> planes only
    bf16gemm<3,0><<<dim3(6, 513), 256, SM>>>(b_xH, b_xL, 256, 0, b_WqT_H, b_WqT_L, 256, 0,
        nullptr, b_qkvH, b_qkvL, 768, NTOK, 768, 256, nullptr, nullptr, nullptr, 0, 768);

    make_wfab<<<256, 256>>>(Wf, Wa, Wb);
    make_bias2<<<1, 256>>>(bf, Wa, ba, Wb, bb);
    sa_kernel<<<MCLUS, 256>>>();
    make_vcab<<<256, 64>>>(Wa, Wb);

    // cap: S = qp @ kc^T (2-prod), row softmax -> P planes
    bf16gemm<2,0><<<dim3(1, 512), 256, SM>>>(b_qkvH + (size_t)MCLUS * 768, b_qkvL + (size_t)MCLUS * 768, 768, 0,
        b_qkvH + 256, b_qkvL + 256, 768, 0, p_Scap, nullptr, nullptr, 64,
        NPATH, 64, 256, nullptr, nullptr, nullptr, 0, MCLUS);
    cap_rowsoft<<<NPATH / 8, 256>>>();

    // cac: S2 = kp @ qc^T (2-prod), col softmax, occ = E^T @ vp / l
    bf16gemm<2,0><<<dim3(1, 512), 256, SM>>>(b_qkvH + (size_t)MCLUS * 768 + 256, b_qkvL + (size_t)MCLUS * 768 + 256, 768, 0,
        b_qkvH, b_qkvL, 768, 0, p_Scac, nullptr, nullptr, 64,
        NPATH, 64, 256, nullptr, nullptr, nullptr, 0, MCLUS);
    colmax_part<<<64, 256>>>();
    colmax_comb<<<1, 64>>>();
    cac_exp<<<64, 256>>>();
    bf16gemm<3,0><<<dim3(2, 1, 32), 256, SM>>>(b_EH, b_EL, 64, 1, vpH, vpL, 768, 1,
        p_occ, nullptr, nullptr, 256, MCLUS, 256, 2048, nullptr, nullptr, nullptr, 1, 256);
    cac_div<<<MCLUS, 256>>>();

    // linear attention
    linprep_kernel<<<NPATH, 256>>>(scl);
    klsum_kernel<<<256, 256>>>();
    zfac_kernel<<<NPATH / 8, 256>>>();
    bf16gemm<3,0><<<dim3(2, 2, 32), 256, SM>>>(b_klH, b_klL, 256, 1, vpH, vpL, 768, 1,
        p_kv, nullptr, nullptr, 256, 256, 256, 2048, nullptr, nullptr, nullptr, 1, 256);
    transpose_cvt<<<dim3(8, 8), dim3(32, 8)>>>(p_kv, 256, 256, 256, 256, b_kvT_H, b_kvT_L, 1, 0);

    conv_kernel<<<2048, 256>>>(dwcw, dwcb);
    // spin = zfac * (ql @ kv) + fm  (planes only)
    bf16gemm<3,0><<<dim3(2, 512), 256, SM>>>(b_qlH, b_qlL, 256, 0, b_kvT_H, b_kvT_L, 256, 0,
        nullptr, b_spinH, b_spinL, 256, NPATH, 256, 256, nullptr, p_zfac, p_spin, 0, 256);

    // small gated scorers (merged)
    gated_pair<<<8, 256>>>(Wa, ba, Wb, bb, Wc);

    // fused gated cross/self
    bf16gemm<2,1><<<dim3(4, 512), 256, SM>>>(b_PH, b_PL, 64, 0, b_vcabT_H, b_vcabT_L, 64, 0,
        p_Acp, nullptr, nullptr, 0, NPATH, 512, 64, ba, bb, Wc, 0, 512);
    bf16gemm<2,1><<<dim3(4, 512), 256, SM>>>(b_spinH, b_spinL, 256, 0, b_WfabT_H, b_WfabT_L, 256, 0,
        p_Asp, nullptr, nullptr, 0, NPATH, 512, 256, p_bfa2, p_bfb2, Wc, 0, 512);

    // fusion pooling
    fmax_small2<<<2, 256>>>();
    fmax_part2<<<dim3(256, 2), 256>>>();
    fmax_comb2<<<2, 256>>>();
    wsum_small2<<<2, 256>>>();
    wsum_planes<<<256, 256>>>(p_Acp, b_PH, b_PL, NPATH, 1, 256, 64, p_fw);
    wsum_planes<<<256, 256>>>(p_Asp, b_spinH, b_spinL, NPATH, 3, 256, 256, p_ft);
    post_both<<<2, 256>>>(Wf, bf);

    fuse_final<<<2, 256>>>(W1, b1, W2, b2, W3a, b3a, W3b, b3b, out);
}

// round 17
// speedup vs baseline: 1.5047x; 1.0122x over previous
#include <cuda_runtime.h>
#include <cuda_bf16.h>
#include <math.h>
#include <stdint.h>

#define NTOK   65586
#define MCLUS  50
#define NPATH  65536
#define DIM    256
#define SCALE  0.0625f

typedef __nv_bfloat16 bf16;

// ---------------- fp32 scratch ----------------------------------------------
__device__ float g_osc[MCLUS * DIM];
__device__ float g_occ[MCLUS * DIM];
__device__ float g_klsum[DIM];
__device__ float g_kv[DIM * DIM];
__device__ float g_zfac[NPATH];
__device__ float g_spin[(size_t)NPATH * DIM];
__device__ float g_Scac[(size_t)NPATH * 64];
__device__ float g_pmax[64 * 64];
__device__ float g_clsum[64];
__device__ float g_Acp[NPATH];
__device__ float g_Asp[NPATH];
__device__ float g_Acc[MCLUS];
__device__ float g_Asc[MCLUS];
__device__ float g_fpart[2 * 256];
__device__ float g_fmax[4];
__device__ float g_fl[4];
__device__ float g_fh[4 * DIM];
__device__ float g_fw[64];
__device__ float g_ft[DIM];
__device__ float g_bfa2[DIM];
__device__ float g_bfb2[DIM];

// ---------------- bf16 hi/lo planes -----------------------------------------
__device__ __align__(16) bf16 qkvH[(size_t)NTOK * 768], qkvL[(size_t)NTOK * 768];
__device__ __align__(16) bf16 xH[(size_t)NTOK * 256],  xL[(size_t)NTOK * 256];
__device__ __align__(16) bf16 WqkvT_H[768 * 256], WqkvT_L[768 * 256];
__device__ __align__(16) bf16 vcabT_H[512 * 64], vcabT_L[512 * 64];
__device__ __align__(16) bf16 WfabT_H[(size_t)512 * 256], WfabT_L[(size_t)512 * 256];
__device__ __align__(16) bf16 kvT_H[256 * 256], kvT_L[256 * 256];
__device__ __align__(16) bf16 qlH[(size_t)NPATH * 256], qlL[(size_t)NPATH * 256];
__device__ __align__(16) bf16 klH[(size_t)NPATH * 256], klL[(size_t)NPATH * 256];
__device__ __align__(16) bf16 PH[(size_t)NPATH * 64],  PL[(size_t)NPATH * 64];
__device__ __align__(16) bf16 EH[(size_t)NPATH * 64],  EL[(size_t)NPATH * 64];
__device__ __align__(16) bf16 spinH[(size_t)NPATH * 256], spinL[(size_t)NPATH * 256];

__device__ __forceinline__ void splitbf(float v, bf16& h, bf16& l) {
    h = __float2bfloat16(v);
    l = __float2bfloat16(v - __bfloat162float(h));
}
__device__ __forceinline__ float recbf(const bf16* H, const bf16* L, size_t i) {
    return __bfloat162float(H[i]) + __bfloat162float(L[i]);
}

__global__ void init_kernel() {
    int t = blockIdx.x * 256 + threadIdx.x;
    int nthr = gridDim.x * 256;
    for (int i = t; i < NPATH; i += nthr) { g_Acp[i] = 0.f; g_Asp[i] = 0.f; }
    if (blockIdx.x == 0) {
        int c = threadIdx.x;
        for (int i = c; i < DIM * DIM; i += 256) g_kv[i] = 0.f;
        for (int i = c; i < MCLUS * DIM; i += 256) g_occ[i] = 0.f;
        if (c < DIM) { g_klsum[c] = 0.f; g_ft[c] = 0.f; }
        if (c < 64) { g_clsum[c] = 0.f; g_fw[c] = 0.f; }
        if (c < 4) g_fl[c] = 0.f;
        for (int i = c; i < 4 * DIM; i += 256) g_fh[i] = 0.f;
    }
}

__global__ void cvt_planar(const float* __restrict__ src, bf16* __restrict__ h,
                           bf16* __restrict__ l, int n) {
    int i = (blockIdx.x * 256 + threadIdx.x) * 4;
    if (i >= n) return;
    float4 v = *(const float4*)(src + i);
    bf16 a, b;
    splitbf(v.x, a, b); h[i+0]=a; l[i+0]=b;
    splitbf(v.y, a, b); h[i+1]=a; l[i+1]=b;
    splitbf(v.z, a, b); h[i+2]=a; l[i+2]=b;
    splitbf(v.w, a, b); h[i+3]=a; l[i+3]=b;
}

__global__ void transpose_cvt(const float* __restrict__ src, int ldsrc,
                              int R, int C, int Rpad,
                              bf16* __restrict__ dH, bf16* __restrict__ dL,
                              int rowMul, int rowOff) {
    __shared__ float t[32][33];
    int r0 = blockIdx.x * 32, c0 = blockIdx.y * 32;
    int tx = threadIdx.x, ty = threadIdx.y;
    for (int i = ty; i < 32; i += 8) {
        int r = r0 + i, c = c0 + tx;
        t[i][tx] = (r < R && c < C) ? src[(size_t)r * ldsrc + c] : 0.f;
    }
    __syncthreads();
    for (int i = ty; i < 32; i += 8) {
        int c = c0 + i, r = r0 + tx;
        if (c < C && r < Rpad) {
            bf16 h, l; splitbf(t[tx][i], h, l);
            size_t o = (size_t)(c * rowMul + rowOff) * Rpad + r;
            dH[o] = h; dL[o] = l;
        }
    }
}

__global__ void make_wfab(const float* __restrict__ Wf,
                          const float* __restrict__ Wa, const float* __restrict__ Wb) {
    __shared__ float wrow[256];
    int c = blockIdx.x, f = threadIdx.x;
    wrow[f] = Wf[c * 256 + f];
    __syncthreads();
    float sa0 = 0.f, sa1 = 0.f, sb0 = 0.f, sb1 = 0.f;
#pragma unroll 8
    for (int d = 0; d < 256; d += 2) {
        float w0 = wrow[d], w1 = wrow[d + 1];
        sa0 += w0 * Wa[d * 256 + f];
        sa1 += w1 * Wa[(d + 1) * 256 + f];
        sb0 += w0 * Wb[d * 256 + f];
        sb1 += w1 * Wb[(d + 1) * 256 + f];
    }
    bf16 h, l;
    splitbf(sa0 + sa1, h, l); WfabT_H[(size_t)(2*f)*256 + c] = h;   WfabT_L[(size_t)(2*f)*256 + c] = l;
    splitbf(sb0 + sb1, h, l); WfabT_H[(size_t)(2*f+1)*256 + c] = h; WfabT_L[(size_t)(2*f+1)*256 + c] = l;
}

__global__ void make_bias2(const float* __restrict__ bfv,
                           const float* __restrict__ Wa, const float* __restrict__ ba,
                           const float* __restrict__ Wb, const float* __restrict__ bb) {
    int f = threadIdx.x;
    float sa0 = ba[f], sa1 = 0.f, sb0 = bb[f], sb1 = 0.f;
#pragma unroll 8
    for (int d = 0; d < 256; d += 2) {
        float v0 = bfv[d], v1 = bfv[d + 1];
        sa0 += v0 * Wa[d * 256 + f];
        sa1 += v1 * Wa[(d + 1) * 256 + f];
        sb0 += v0 * Wb[d * 256 + f];
        sb1 += v1 * Wb[(d + 1) * 256 + f];
    }
    g_bfa2[f] = sa0 + sa1; g_bfb2[f] = sb0 + sb1;
}

__global__ void make_vcab(const float* __restrict__ Wa, const float* __restrict__ Wb) {
    int f = blockIdx.x, j = threadIdx.x;
    float sa0 = 0.f, sa1 = 0.f, sb0 = 0.f, sb1 = 0.f;
    if (j < MCLUS) {
#pragma unroll 8
        for (int c = 0; c < 256; c += 2) {
            float v0 = recbf(qkvH, qkvL, (size_t)j * 768 + 512 + c);
            float v1 = recbf(qkvH, qkvL, (size_t)j * 768 + 512 + c + 1);
            sa0 += v0 * Wa[c * 256 + f];
            sa1 += v1 * Wa[(c + 1) * 256 + f];
            sb0 += v0 * Wb[c * 256 + f];
            sb1 += v1 * Wb[(c + 1) * 256 + f];
        }
    }
    bf16 h, l;
    splitbf(sa0 + sa1, h, l); vcabT_H[(2*f)*64 + j] = h;   vcabT_L[(2*f)*64 + j] = l;
    splitbf(sb0 + sb1, h, l); vcabT_H[(2*f+1)*64 + j] = h; vcabT_L[(2*f+1)*64 + j] = l;
}

// ============================================================================
// bf16 planar GEMM.
// EPI=0: normal epilogue.  EPI=1: fused gated scorer.
// EPI=2: fused row-softmax (cap) — N=64, one block column; writes P planes.
// NPROD=2 skips the B-lo plane entirely (staging + ldsm).
// ============================================================================
#define PSTRIDE 5120
#define STSTRIDE 20480

__device__ __forceinline__ void cp16(unsigned dst, const void* src, bool valid) {
    int sz = valid ? 16 : 0;
    asm volatile("cp.async.cg.shared.global [%0], [%1], 16, %2;\n"
                 :: "r"(dst), "l"(src), "r"(sz));
}
__device__ __forceinline__ void mma_bf16(float* c, const unsigned* a, const unsigned* b) {
    asm volatile(
        "mma.sync.aligned.m16n8k16.row.col.f32.bf16.bf16.f32 "
        "{%0,%1,%2,%3},{%4,%5,%6,%7},{%8,%9},{%0,%1,%2,%3};\n"
        : "+f"(c[0]), "+f"(c[1]), "+f"(c[2]), "+f"(c[3])
        : "r"(a[0]), "r"(a[1]), "r"(a[2]), "r"(a[3]), "r"(b[0]), "r"(b[1]));
}
__device__ __forceinline__ void ldsm4(unsigned* r, unsigned addr) {
    asm volatile("ldmatrix.sync.aligned.m8n8.x4.shared.b16 {%0,%1,%2,%3}, [%4];"
        : "=r"(r[0]), "=r"(r[1]), "=r"(r[2]), "=r"(r[3]) : "r"(addr));
}

template<int NPROD>
__device__ __forceinline__ void stage_tile(
    bf16* sb,
    const bf16* __restrict__ Ahi, const bf16* __restrict__ Alo, int lda, int transA,
    const bf16* __restrict__ Bhi, const bf16* __restrict__ Blo, int ldb, int transB,
    int m0, int n0, int k0, int M, int nBound, int tid)
{
    int r = tid & 127;
    int kh = (tid >> 7) << 4;
    if (!transB) {
        bool v = (n0 + r) < nBound;
        const bf16* gh = v ? (Bhi + (size_t)(n0 + r) * ldb + k0 + kh) : Bhi;
        unsigned sh = (unsigned)__cvta_generic_to_shared(sb + 2*PSTRIDE + r*40 + kh);
        cp16(sh, gh, v); cp16(sh + 16, gh + 8, v);
        if (NPROD == 3) {
            const bf16* gl = v ? (Blo + (size_t)(n0 + r) * ldb + k0 + kh) : Blo;
            unsigned sl = (unsigned)__cvta_generic_to_shared(sb + 3*PSTRIDE + r*40 + kh);
            cp16(sl, gl, v); cp16(sl + 16, gl + 8, v);
        }
    } else {
        int n8 = (tid & 15) * 8;
        int kq = tid >> 4;
        bf16 z = __float2bfloat16(0.f);
#pragma unroll
        for (int e = 0; e < 2; e++) {
            int kk = kq + (e << 4);
            const bf16* gh = Bhi + (size_t)(k0 + kk) * ldb + n0 + n8;
            const bf16* gl = Blo + (size_t)(k0 + kk) * ldb + n0 + n8;
            if (n0 + n8 + 7 < nBound) {
                uint4 vh = *(const uint4*)gh;
                const bf16* eh = (const bf16*)&vh;
#pragma unroll
                for (int j = 0; j < 8; j++) sb[2*PSTRIDE + (n8+j)*40 + kk] = eh[j];
                if (NPROD == 3) {
                    uint4 vl = *(const uint4*)gl;
                    const bf16* el = (const bf16*)&vl;
#pragma unroll
                    for (int j = 0; j < 8; j++) sb[3*PSTRIDE + (n8+j)*40 + kk] = el[j];
                }
            } else {
#pragma unroll
                for (int j = 0; j < 8; j++) {
                    bool ok = (n0 + n8 + j) < nBound;
                    sb[2*PSTRIDE + (n8+j)*40 + kk] = ok ? gh[j] : z;
                    if (NPROD == 3) sb[3*PSTRIDE + (n8+j)*40 + kk] = ok ? gl[j] : z;
                }
            }
        }
    }
    if (!transA) {
        bool v = (m0 + r) < M;
        const bf16* gh = v ? (Ahi + (size_t)(m0 + r) * lda + k0 + kh) : Ahi;
        const bf16* gl = v ? (Alo + (size_t)(m0 + r) * lda + k0 + kh) : Alo;
        unsigned sh = (unsigned)__cvta_generic_to_shared(sb + r*40 + kh);
        unsigned sl = (unsigned)__cvta_generic_to_shared(sb + PSTRIDE + r*40 + kh);
        cp16(sh, gh, v); cp16(sh + 16, gh + 8, v);
        cp16(sl, gl, v); cp16(sl + 16, gl + 8, v);
    } else {
        int m8 = (tid & 15) * 8;
        int kq = tid >> 4;
        bf16 z = __float2bfloat16(0.f);
#pragma unroll
        for (int e = 0; e < 2; e++) {
            int kk = kq + (e << 4);
            const bf16* gh = Ahi + (size_t)(k0 + kk) * lda + m0 + m8;
            const bf16* gl = Alo + (size_t)(k0 + kk) * lda + m0 + m8;
            if (m0 + m8 + 7 < lda) {
                uint4 vh = *(const uint4*)gh;
                uint4 vl = *(const uint4*)gl;
                const bf16* eh = (const bf16*)&vh;
                const bf16* el = (const bf16*)&vl;
#pragma unroll
                for (int j = 0; j < 8; j++) {
                    sb[(m8+j)*40 + kk] = eh[j];
                    sb[PSTRIDE + (m8+j)*40 + kk] = el[j];
                }
            } else {
#pragma unroll
                for (int j = 0; j < 8; j++) {
                    bool ok = (m0 + m8 + j) < lda;
                    sb[(m8+j)*40 + kk] = ok ? gh[j] : z;
                    sb[PSTRIDE + (m8+j)*40 + kk] = ok ? gl[j] : z;
                }
            }
        }
    }
}

template<int NPROD, int EPI>
__global__ void __launch_bounds__(256, 2) bf16gemm(
    const bf16* __restrict__ Ahi, const bf16* __restrict__ Alo, int lda, int transA,
    const bf16* __restrict__ Bhi, const bf16* __restrict__ Blo, int ldb, int transB,
    float* __restrict__ Cf, bf16* __restrict__ Chi, bf16* __restrict__ Clo, int ldc,
    int M, int N, int kRange,
    const float* __restrict__ bias, const float* __restrict__ rowScale,
    const float* __restrict__ addSrc, int atomicOut, int nBound)
{
    extern __shared__ bf16 smdyn[];
    int tid = threadIdx.x;
    int w = tid >> 5, lane = tid & 31;
    int wm = w >> 2, wn = w & 3;
    int g = lane >> 2, tig = lane & 3;

    int m0 = blockIdx.y * 128;
    int n0 = blockIdx.x * 128;
    int k0beg = blockIdx.z * kRange;
    int nIter = kRange >> 5;

    unsigned uBase = (unsigned)__cvta_generic_to_shared(smdyn);
    unsigned laneA  = (unsigned)((lane & 15) * 80 + (lane >> 4) * 16);
    unsigned laneB4 = (unsigned)((lane & 7) * 80 + ((lane >> 3) & 1) * 16 + ((lane >> 4) & 1) * 640);

    float acc[4][4][4];
#pragma unroll
    for (int i = 0; i < 4; i++)
#pragma unroll
        for (int j = 0; j < 4; j++)
#pragma unroll
            for (int q = 0; q < 4; q++) acc[i][j][q] = 0.f;

    stage_tile<NPROD>(smdyn, Ahi, Alo, lda, transA, Bhi, Blo, ldb, transB,
                      m0, n0, k0beg, M, nBound, tid);
    asm volatile("cp.async.commit_group;\n");

    for (int it = 0; it < nIter; it++) {
        if (it + 1 < nIter) {
            stage_tile<NPROD>(smdyn + ((it+1)&1)*STSTRIDE, Ahi, Alo, lda, transA,
                              Bhi, Blo, ldb, transB, m0, n0, k0beg + (it+1)*32, M, nBound, tid);
            asm volatile("cp.async.commit_group;\n");
            asm volatile("cp.async.wait_group 1;\n");
        } else {
            asm volatile("cp.async.wait_group 0;\n");
        }
        __syncthreads();

        unsigned uB = uBase + (unsigned)((it & 1) * STSTRIDE * 2);
#pragma unroll
        for (int ks = 0; ks < 2; ks++) {
            unsigned kB = (unsigned)(ks * 32);
            unsigned bh[4][2], bl[4][2];
#pragma unroll
            for (int ntp = 0; ntp < 2; ntp++) {
                unsigned ad = uB + (unsigned)(2*PSTRIDE*2 + (wn*32 + ntp*16)*80) + kB + laneB4;
                unsigned t4[4];
                ldsm4(t4, ad);
                bh[2*ntp][0] = t4[0]; bh[2*ntp][1] = t4[1];
                bh[2*ntp+1][0] = t4[2]; bh[2*ntp+1][1] = t4[3];
                if (NPROD == 3) {
                    ldsm4(t4, ad + PSTRIDE*2);
                    bl[2*ntp][0] = t4[0]; bl[2*ntp][1] = t4[1];
                    bl[2*ntp+1][0] = t4[2]; bl[2*ntp+1][1] = t4[3];
                }
            }
#pragma unroll
            for (int mt = 0; mt < 4; mt++) {
                unsigned ad = uB + (unsigned)((wm*64 + mt*16)*80) + kB + laneA;
                unsigned ah[4], al[4];
                ldsm4(ah, ad);
                ldsm4(al, ad + PSTRIDE*2);
#pragma unroll
                for (int nt = 0; nt < 4; nt++) mma_bf16(acc[mt][nt], ah, bh[nt]);
#pragma unroll
                for (int nt = 0; nt < 4; nt++) mma_bf16(acc[mt][nt], al, bh[nt]);
                if (NPROD == 3) {
#pragma unroll
                    for (int nt = 0; nt < 4; nt++) mma_bf16(acc[mt][nt], ah, bl[nt]);
                }
            }
        }
        __syncthreads();
    }

    if (EPI == 1) {
        float sacc[4][2];
#pragma unroll
        for (int mt = 0; mt < 4; mt++) { sacc[mt][0] = 0.f; sacc[mt][1] = 0.f; }
#pragma unroll
        for (int nt = 0; nt < 4; nt++) {
            int c = n0 + wn * 32 + nt * 8 + tig * 2;
            int f = c >> 1;
            float bav = bias[f], bbv = rowScale[f], wcv = addSrc[f];
#pragma unroll
            for (int mt = 0; mt < 4; mt++) {
#pragma unroll
                for (int h2 = 0; h2 < 2; h2++) {
                    float v0 = acc[mt][nt][h2*2 + 0] + bav;
                    float v1 = acc[mt][nt][h2*2 + 1] + bbv;
                    float p = tanhf(v0) * (1.f / (1.f + expf(-v1))) * wcv;
                    sacc[mt][h2] += p;
                }
            }
        }
#pragma unroll
        for (int mt = 0; mt < 4; mt++) {
#pragma unroll
            for (int h2 = 0; h2 < 2; h2++) {
                float s = sacc[mt][h2];
                s += __shfl_xor_sync(0xffffffffu, s, 1);
                s += __shfl_xor_sync(0xffffffffu, s, 2);
                if (tig == 0) {
                    int r = m0 + wm * 64 + mt * 16 + g + h2 * 8;
                    if (r < M) atomicAdd(&Cf[r], s);
                }
            }
        }
        return;
    }

    if (EPI == 2) {
        // fused row softmax (cap): N=64 in this block column; valid cols < nBound.
        // Row r = m0 + wm*64 + mt*16 + h2*8 + g; cols split across warps wn=0,1.
        float* sx = (float*)smdyn;          // [2][128] half maxima
        float* sy = sx + 256;               // [2][128] half sums
        bool act = (wn < 2);
        float vmax[4][2];
#pragma unroll
        for (int mt = 0; mt < 4; mt++)
#pragma unroll
            for (int h2 = 0; h2 < 2; h2++) {
                float m = -1e30f;
                if (act) {
#pragma unroll
                    for (int nt = 0; nt < 4; nt++) {
                        int c = wn * 32 + nt * 8 + tig * 2;
                        float v0 = (c < nBound) ? acc[mt][nt][h2*2 + 0] : -1e30f;
                        float v1 = (c + 1 < nBound) ? acc[mt][nt][h2*2 + 1] : -1e30f;
                        m = fmaxf(m, fmaxf(v0, v1));
                    }
                }
                m = fmaxf(m, __shfl_xor_sync(0xffffffffu, m, 1));
                m = fmaxf(m, __shfl_xor_sync(0xffffffffu, m, 2));
                vmax[mt][h2] = m;
            }
        if (act && tig == 0) {
#pragma unroll
            for (int mt = 0; mt < 4; mt++)
#pragma unroll
                for (int h2 = 0; h2 < 2; h2++)
                    sx[wn * 128 + wm * 64 + mt * 16 + h2 * 8 + g] = vmax[mt][h2];
        }
        __syncthreads();
        float esum[4][2];
#pragma unroll
        for (int mt = 0; mt < 4; mt++)
#pragma unroll
            for (int h2 = 0; h2 < 2; h2++) {
                int rl = wm * 64 + mt * 16 + h2 * 8 + g;
                float m = fmaxf(sx[rl], sx[128 + rl]);
                float s = 0.f;
                if (act) {
#pragma unroll
                    for (int nt = 0; nt < 4; nt++) {
                        int c = wn * 32 + nt * 8 + tig * 2;
                        float e0 = (c < nBound) ? expf((acc[mt][nt][h2*2 + 0] - m) * SCALE) : 0.f;
                        float e1 = (c + 1 < nBound) ? expf((acc[mt][nt][h2*2 + 1] - m) * SCALE) : 0.f;
                        acc[mt][nt][h2*2 + 0] = e0;
                        acc[mt][nt][h2*2 + 1] = e1;
                        s += e0 + e1;
                    }
                }
                s += __shfl_xor_sync(0xffffffffu, s, 1);
                s += __shfl_xor_sync(0xffffffffu, s, 2);
                esum[mt][h2] = s;
            }
        if (act && tig == 0) {
#pragma unroll
            for (int mt = 0; mt < 4; mt++)
#pragma unroll
                for (int h2 = 0; h2 < 2; h2++)
                    sy[wn * 128 + wm * 64 + mt * 16 + h2 * 8 + g] = esum[mt][h2];
        }
        __syncthreads();
        if (act) {
#pragma unroll
            for (int mt = 0; mt < 4; mt++)
#pragma unroll
                for (int h2 = 0; h2 < 2; h2++) {
                    int rl = wm * 64 + mt * 16 + h2 * 8 + g;
                    float inv = 1.f / (sy[rl] + sy[128 + rl]);
                    size_t rowbase = (size_t)(m0 + rl) * ldc;
#pragma unroll
                    for (int nt = 0; nt < 4; nt++) {
                        int c = wn * 32 + nt * 8 + tig * 2;
                        float p0 = acc[mt][nt][h2*2 + 0] * inv;
                        float p1 = acc[mt][nt][h2*2 + 1] * inv;
                        __nv_bfloat162 hv, lv;
                        bf16 h, l;
                        splitbf(p0, h, l); hv.x = h; lv.x = l;
                        splitbf(p1, h, l); hv.y = h; lv.y = l;
                        *(__nv_bfloat162*)&Chi[rowbase + c] = hv;
                        *(__nv_bfloat162*)&Clo[rowbase + c] = lv;
                    }
                }
        }
        return;
    }

#pragma unroll
    for (int mt = 0; mt < 4; mt++) {
#pragma unroll
        for (int nt = 0; nt < 4; nt++) {
            int rA = m0 + wm * 64 + mt * 16 + g;
            int c = n0 + wn * 32 + nt * 8 + tig * 2;
            if (c >= N) continue;
#pragma unroll
            for (int h2 = 0; h2 < 2; h2++) {
                int r = rA + h2 * 8;
                if (r >= M) continue;
                float v0 = acc[mt][nt][h2*2 + 0];
                float v1 = acc[mt][nt][h2*2 + 1];
                size_t idx = (size_t)r * ldc + c;
                if (atomicOut) {
                    atomicAdd(&Cf[idx], v0);
                    atomicAdd(&Cf[idx+1], v1);
                    continue;
                }
                if (rowScale) { float rs = rowScale[r]; v0 *= rs; v1 *= rs; }
                if (addSrc) { v0 += addSrc[idx]; v1 += addSrc[idx+1]; }
                if (bias) { v0 += bias[c]; v1 += bias[c+1]; }
                if (Cf) *(float2*)&Cf[idx] = make_float2(v0, v1);
                if (Chi) {
                    __nv_bfloat162 hv, lv;
                    bf16 h, l;
                    splitbf(v0, h, l); hv.x = h; lv.x = l;
                    splitbf(v1, h, l); hv.y = h; lv.y = l;
                    *(__nv_bfloat162*)&Chi[idx] = hv;
                    *(__nv_bfloat162*)&Clo[idx] = lv;
                }
            }
        }
    }
}

// ---------------- small kernels ---------------------------------------------
__global__ void sa_kernel() {
    __shared__ float qrow[DIM], sc[MCLUS], pr[MCLUS];
    int i = blockIdx.x, c = threadIdx.x;
    qrow[c] = recbf(qkvH, qkvL, (size_t)i * 768 + c);
    __syncthreads();
    if (c < MCLUS) {
        float s = 0.f;
        for (int k = 0; k < DIM; k++)
            s += qrow[k] * recbf(qkvH, qkvL, (size_t)c * 768 + 256 + k);
        sc[c] = s * SCALE;
    }
    __syncthreads();
    float m = -1e30f;
    for (int t = 0; t < MCLUS; t++) m = fmaxf(m, sc[t]);
    if (c < MCLUS) pr[c] = expf(sc[c] - m);
    __syncthreads();
    float sum = 0.f;
    for (int t = 0; t < MCLUS; t++) sum += pr[t];
    float o = 0.f;
    for (int t = 0; t < MCLUS; t++) o += pr[t] * recbf(qkvH, qkvL, (size_t)t * 768 + 512 + c);
    g_osc[i * DIM + c] = o / sum;
}

__global__ void colmax_part() {
    int col = threadIdx.x & 63, rq = threadIdx.x >> 6;
    float m = -1e30f;
    int r0 = blockIdx.x * 1024;
    for (int r = r0 + rq; r < r0 + 1024; r += 4) m = fmaxf(m, g_Scac[(size_t)r * 64 + col]);
    __shared__ float sm[256];
    sm[threadIdx.x] = m;
    __syncthreads();
    if (rq == 0)
        g_pmax[blockIdx.x * 64 + col] =
            fmaxf(fmaxf(sm[col], sm[64+col]), fmaxf(sm[128+col], sm[192+col]));
}
// cac_exp now folds the global-column-max reduction in directly
__global__ void cac_exp() {
    int col = threadIdx.x & 63, rq = threadIdx.x >> 6;
    float mx = -1e30f;
#pragma unroll 8
    for (int b = 0; b < 64; b++) mx = fmaxf(mx, g_pmax[b * 64 + col]);
    float s = 0.f;
    int r0 = blockIdx.x * 1024;
    for (int r = r0 + rq; r < r0 + 1024; r += 4) {
        float v = g_Scac[(size_t)r * 64 + col];
        float e = (col < MCLUS) ? expf((v - mx) * SCALE) : 0.f;
        bf16 h, l; splitbf(e, h, l);
        EH[(size_t)r * 64 + col] = h; EL[(size_t)r * 64 + col] = l;
        s += e;
    }
    __shared__ float sm[256];
    sm[threadIdx.x] = s;
    __syncthreads();
    if (rq == 0 && col < MCLUS)
        atomicAdd(&g_clsum[col], sm[col] + sm[64+col] + sm[128+col] + sm[192+col]);
}
__global__ void cac_div() {
    int i = blockIdx.x, c = threadIdx.x;
    g_occ[i * DIM + c] /= g_clsum[i];
}

__global__ void linprep_kernel(const float* __restrict__ scale_linear) {
    int i = blockIdx.x, c = threadIdx.x;
    size_t tok = (size_t)(MCLUS + i) * 768;
    float sp = logf(1.f + expf(scale_linear[c]));
    float q = recbf(qkvH, qkvL, tok + c);
    float k = recbf(qkvH, qkvL, tok + 256 + c);
    float tq = (fmaxf(q, 0.f) + 1e-6f) / sp;
    float tk = (fmaxf(k, 0.f) + 1e-6f) / sp;
    float uq = tq*tq*tq, uk = tk*tk*tk;
    __shared__ float4 red[256];
    red[c] = make_float4(tq*tq, uq*uq, tk*tk, uk*uk);
    __syncthreads();
    for (int s = 128; s > 0; s >>= 1) {
        if (c < s) {
            float4 a = red[c], b = red[c + s];
            red[c] = make_float4(a.x+b.x, a.y+b.y, a.z+b.z, a.w+b.w);
        }
        __syncthreads();
    }
    float4 t = red[0];
    float vq = uq * sqrtf(t.x) / sqrtf(t.y);
    float vk = uk * sqrtf(t.z) / sqrtf(t.w);
    size_t o = (size_t)i * DIM + c;
    bf16 h, l;
    splitbf(vq, h, l); qlH[o] = h; qlL[o] = l;
    splitbf(vk, h, l); klH[o] = h; klL[o] = l;
}

__global__ void klsum_kernel() {
    int c = threadIdx.x;
    int r0 = blockIdx.x * (NPATH / 256);
    float s = 0.f;
    for (int r = r0; r < r0 + NPATH / 256; r++)
        s += recbf(klH, klL, (size_t)r * DIM + c);
    atomicAdd(&g_klsum[c], s);
}
__global__ void zfac_kernel() {
    int warp = threadIdx.x >> 5, lane = threadIdx.x & 31;
    int row = blockIdx.x * 8 + warp;
    float s = 0.f;
    for (int cc = lane; cc < DIM; cc += 32)
        s += recbf(qlH, qlL, (size_t)row * DIM + cc) * g_klsum[cc];
    for (int o = 16; o; o >>= 1) s += __shfl_down_sync(0xffffffffu, s, o);
    if (!lane) g_zfac[row] = 1.f / (s + 1e-6f);
}

__global__ void conv_kernel(const float* __restrict__ dwc_w,
                            const float* __restrict__ dwc_b) {
    int d = threadIdx.x;
    int b = blockIdx.x;
    int w0 = (b >> 5) * 4;
    int h0 = (b & 31) * 8;
    float wt[25];
#pragma unroll
    for (int i = 0; i < 25; i++) wt[i] = dwc_w[d * 25 + i];
    float bias = dwc_b[d];
    float acc[4][8];
#pragma unroll
    for (int ow = 0; ow < 4; ow++)
#pragma unroll
        for (int oh = 0; oh < 8; oh++) acc[ow][oh] = bias;

#pragma unroll
    for (int dwa = 0; dwa < 8; dwa++) {
        int wa = w0 + dwa - 2;
        if ((unsigned)wa >= 256u) continue;
#pragma unroll
        for (int dhb = 0; dhb < 12; dhb++) {
            int hb = h0 + dhb - 2;
            if ((unsigned)hb >= 256u) continue;
            float val = recbf(qkvH, qkvL, (size_t)(MCLUS + wa * 256 + hb) * 768 + 512 + d);
#pragma unroll
            for (int ow = 0; ow < 4; ow++) {
                int a = dwa - ow;
                if (a < 0 || a > 4) continue;
#pragma unroll
                for (int oh = 0; oh < 8; oh++) {
                    int bo = dhb - oh;
                    if (bo < 0 || bo > 4) continue;
                    acc[ow][oh] += val * wt[a * 5 + bo];
                }
            }
        }
    }
#pragma unroll
    for (int ow = 0; ow < 4; ow++)
#pragma unroll
        for (int oh = 0; oh < 8; oh++)
            g_spin[(size_t)((w0 + ow) * 256 + h0 + oh) * DIM + d] = acc[ow][oh];
}

__global__ void gated_pair(const float* __restrict__ Wa, const float* __restrict__ ba,
                           const float* __restrict__ Wb, const float* __restrict__ bb,
                           const float* __restrict__ Wc)
{
    const float* T = (blockIdx.x < 4) ? g_occ : g_osc;
    float* Aout = (blockIdx.x < 4) ? g_Acc : g_Asc;
    int row0 = (blockIdx.x & 3) * 16;
    __shared__ float ts[16 * DIM];
    int c = threadIdx.x;
#pragma unroll
    for (int r = 0; r < 16; r++)
        ts[r * DIM + c] = (row0 + r < MCLUS) ? T[(size_t)(row0 + r) * DIM + c] : 0.f;
    __syncthreads();
    float aa[16], gg[16];
    float bav = ba[c], bbv = bb[c];
#pragma unroll
    for (int r = 0; r < 16; r++) { aa[r] = bav; gg[r] = bbv; }
    for (int k = 0; k < DIM; k++) {
        float wa = Wa[k * DIM + c];
        float wb = Wb[k * DIM + c];
#pragma unroll
        for (int r = 0; r < 16; r++) {
            float t = ts[r * DIM + k];
            aa[r] += t * wa; gg[r] += t * wb;
        }
    }
    float wcv = Wc[c];
    __syncthreads();
#pragma unroll
    for (int r = 0; r < 16; r++) {
        float a = tanhf(aa[r]);
        float g2 = 1.f / (1.f + expf(-gg[r]));
        ts[r * DIM + c] = a * g2 * wcv;
    }
    __syncthreads();
    int wid = c >> 5, lane = c & 31;
    for (int r = wid; r < 16; r += 8) {
        float s = 0.f;
        for (int cc = lane; cc < DIM; cc += 32) s += ts[r * DIM + cc];
#pragma unroll
        for (int o = 16; o; o >>= 1) s += __shfl_down_sync(0xffffffffu, s, o);
        if (!lane && row0 + r < MCLUS) Aout[row0 + r] = s;
    }
}

__global__ void fmax_small2() {
    const float* A = blockIdx.x ? g_Asc : g_Acc;
    int slot = blockIdx.x ? 2 : 0;
    __shared__ float red[256];
    int t = threadIdx.x;
    float m = -1e30f;
    for (int r = t; r < MCLUS; r += 256) m = fmaxf(m, A[r]);
    red[t] = m;
    __syncthreads();
    for (int s = 128; s > 0; s >>= 1) {
        if (t < s) red[t] = fmaxf(red[t], red[t + s]);
        __syncthreads();
    }
    if (!t) g_fmax[slot] = red[0];
}

__global__ void fmax_part2() {
    const float* A = blockIdx.y ? g_Asp : g_Acp;
    int i = blockIdx.x * 256 + threadIdx.x;
    float m = A[i];
    int lane = threadIdx.x & 31, warp = threadIdx.x >> 5;
#pragma unroll
    for (int o = 16; o; o >>= 1) m = fmaxf(m, __shfl_xor_sync(0xffffffffu, m, o));
    __shared__ float wred[8];
    if (lane == 0) wred[warp] = m;
    __syncthreads();
    if (threadIdx.x == 0) {
        float mm = wred[0];
#pragma unroll
        for (int wq = 1; wq < 8; wq++) mm = fmaxf(mm, wred[wq]);
        g_fpart[blockIdx.y * 256 + blockIdx.x] = mm;
    }
}
__global__ void fmax_comb2() {
    int pslot = blockIdx.x;
    int slot = pslot ? 3 : 1;
    int t = threadIdx.x;
    float m = g_fpart[pslot * 256 + t];
    int lane = t & 31, warp = t >> 5;
#pragma unroll
    for (int o = 16; o; o >>= 1) m = fmaxf(m, __shfl_xor_sync(0xffffffffu, m, o));
    __shared__ float wred[8];
    if (lane == 0) wred[warp] = m;
    __syncthreads();
    if (t == 0) {
        float mm = wred[0];
#pragma unroll
        for (int wq = 1; wq < 8; wq++) mm = fmaxf(mm, wred[wq]);
        g_fmax[slot] = mm;
    }
}

__global__ void wsum_small2() {
    const float* A = blockIdx.x ? g_Asc : g_Acc;
    const float* X = blockIdx.x ? g_osc : g_occ;
    int slot = blockIdx.x ? 2 : 0;
    __shared__ float se[64];
    int c = threadIdx.x;
    float mx = g_fmax[slot];
    if (c < MCLUS) se[c] = expf(A[c] - mx);
    __syncthreads();
    float h = 0.f;
    for (int t = 0; t < MCLUS; t++) h += se[t] * X[(size_t)t * DIM + c];
    g_fh[slot * DIM + c] = h;
    if (c == 0) {
        float lp = 0.f;
        for (int t = 0; t < MCLUS; t++) lp += se[t];
        g_fl[slot] = lp;
    }
}

__global__ void wsum_planes(const float* __restrict__ A,
                            const bf16* __restrict__ XH, const bf16* __restrict__ XL,
                            int n, int slot, int rpb, int width, float* __restrict__ outv) {
    __shared__ float se[256];
    int c = threadIdx.x;
    int start = blockIdx.x * rpb;
    int end = min(n, start + rpb);
    float mx = g_fmax[slot];
    float h = 0.f, lpart = 0.f;
    for (int r0 = start; r0 < end; r0 += 256) {
        int cnt = min(256, end - r0);
        if (c < cnt) se[c] = expf(A[r0 + c] - mx);
        __syncthreads();
        if (c < width)
            for (int t = 0; t < cnt; t++) {
                size_t idx = (size_t)(r0 + t) * width + c;
                h += se[t] * (__bfloat162float(XH[idx]) + __bfloat162float(XL[idx]));
            }
        if (c == 0) for (int t = 0; t < cnt; t++) lpart += se[t];
        __syncthreads();
    }
    if (c < width) atomicAdd(&outv[c], h);
    if (c == 0) atomicAdd(&g_fl[slot], lpart);
}

__global__ void post_both(const float* __restrict__ Wf, const float* __restrict__ bfv) {
    int c = threadIdx.x;
    if (blockIdx.x == 0) {
        float s = 0.f;
        for (int j = 0; j < MCLUS; j++)
            s += g_fw[j] * recbf(qkvH, qkvL, (size_t)j * 768 + 512 + c);
        g_fh[1 * DIM + c] = s;
    } else {
        float s0 = 0.f, s1 = 0.f;
#pragma unroll 8
        for (int d = 0; d < 256; d += 2) {
            s0 += g_ft[d] * Wf[d * 256 + c];
            s1 += g_ft[d + 1] * Wf[(d + 1) * 256 + c];
        }
        g_fh[3 * DIM + c] = s0 + s1 + bfv[c] * g_fl[3];
    }
}

__global__ void fuse_final(const float* __restrict__ W1, const float* __restrict__ b1,
                           const float* __restrict__ W2, const float* __restrict__ b2,
                           const float* __restrict__ W3a, const float* __restrict__ b3a,
                           const float* __restrict__ W3b, const float* __restrict__ b3b,
                           float* __restrict__ out)
{
    __shared__ float v0[DIM], v1[DIM], hb2[2 * DIM], ub[DIM];
    int f = blockIdx.x, c = threadIdx.x;
    int s0 = f * 2, s1 = f * 2 + 1;
    v0[c] = g_fh[s0 * DIM + c] / g_fl[s0];
    v1[c] = g_fh[s1 * DIM + c] / g_fl[s1];
    __syncthreads();
    float h1 = b1[c], h2 = b2[c];
    for (int k = 0; k < DIM; k++) {
        h1 += v0[k] * W1[k * DIM + c];
        h2 += v1[k] * W2[k * DIM + c];
    }
    hb2[c] = fmaxf(h1, 0.f);
    hb2[DIM + c] = fmaxf(h2, 0.f);
    __syncthreads();
    float u = b3a[c];
    for (int k = 0; k < 2 * DIM; k++) u += hb2[k] * W3a[k * DIM + c];
    ub[c] = fmaxf(u, 0.f);
    __syncthreads();
    float o = b3b[c];
    for (int k = 0; k < DIM; k++) o += ub[k] * W3b[k * DIM + c];
    out[f * DIM + c] = fmaxf(o, 0.f);
}

// ---------------------------------------------------------------------------
extern "C" void kernel_launch(void* const* d_in, const int* in_sizes, int n_in,
                              void* d_out, int out_size) {
    const float* x   = (const float*)d_in[0];
    const float* Wqkv= (const float*)d_in[1];
    const float* scl = (const float*)d_in[2];
    const float* dwcw= (const float*)d_in[3];
    const float* dwcb= (const float*)d_in[4];
    const float* Wa  = (const float*)d_in[5];
    const float* ba  = (const float*)d_in[6];
    const float* Wb  = (const float*)d_in[7];
    const float* bb  = (const float*)d_in[8];
    const float* Wc  = (const float*)d_in[9];
    const float* W1  = (const float*)d_in[11];
    const float* b1  = (const float*)d_in[12];
    const float* W2  = (const float*)d_in[13];
    const float* b2  = (const float*)d_in[14];
    const float* W3a = (const float*)d_in[15];
    const float* b3a = (const float*)d_in[16];
    const float* W3b = (const float*)d_in[17];
    const float* b3b = (const float*)d_in[18];
    const float* Wf  = (const float*)d_in[19];
    const float* bf  = (const float*)d_in[20];
    float* out = (float*)d_out;

    cudaFuncSetAttribute(bf16gemm<3,0>, cudaFuncAttributeMaxDynamicSharedMemorySize, 81920);
    cudaFuncSetAttribute(bf16gemm<2,0>, cudaFuncAttributeMaxDynamicSharedMemorySize, 81920);
    cudaFuncSetAttribute(bf16gemm<2,1>, cudaFuncAttributeMaxDynamicSharedMemorySize, 81920);
    cudaFuncSetAttribute(bf16gemm<2,2>, cudaFuncAttributeMaxDynamicSharedMemorySize, 81920);
    const int SM = 81920;

#define SYM(p, s) float* p; cudaGetSymbolAddress((void**)&p, s)
    SYM(p_kv, g_kv);
    SYM(p_spin, g_spin); SYM(p_zfac, g_zfac);
    SYM(p_occ, g_occ);
    SYM(p_Acp, g_Acp); SYM(p_Asp, g_Asp);
    SYM(p_Scac, g_Scac);
    SYM(p_fw, g_fw); SYM(p_ft, g_ft);
    SYM(p_bfa2, g_bfa2); SYM(p_bfb2, g_bfb2);
#define BSYM(p, s) bf16* p; cudaGetSymbolAddress((void**)&p, s)
    BSYM(b_qkvH, qkvH); BSYM(b_qkvL, qkvL); BSYM(b_xH, xH); BSYM(b_xL, xL);
    BSYM(b_WqT_H, WqkvT_H); BSYM(b_WqT_L, WqkvT_L);
    BSYM(b_vcabT_H, vcabT_H); BSYM(b_vcabT_L, vcabT_L);
    BSYM(b_WfabT_H, WfabT_H); BSYM(b_WfabT_L, WfabT_L);
    BSYM(b_kvT_H, kvT_H); BSYM(b_kvT_L, kvT_L);
    BSYM(b_qlH, qlH); BSYM(b_qlL, qlL); BSYM(b_klH, klH); BSYM(b_klL, klL);
    BSYM(b_PH, PH); BSYM(b_PL, PL); BSYM(b_EH, EH); BSYM(b_EL, EL);
    BSYM(b_spinH, spinH); BSYM(b_spinL, spinL);

    const bf16* vpH = b_qkvH + (size_t)MCLUS * 768 + 512;
    const bf16* vpL = b_qkvL + (size_t)MCLUS * 768 + 512;

    // launches 1-3, qkv GEMM at #4 (ncu capture slot)
    init_kernel<<<64, 256>>>();
    cvt_planar<<<(NTOK * 256 / 4 + 255) / 256, 256>>>(x, b_xH, b_xL, NTOK * 256);
    transpose_cvt<<<dim3(8, 24), dim3(32, 8)>>>(Wqkv, 768, 256, 768, 256, b_WqT_H, b_WqT_L, 1, 0);

    // #4: qkv = x @ Wqkv -> planes only
    bf16gemm<3,0><<<dim3(6, 513), 256, SM>>>(b_xH, b_xL, 256, 0, b_WqT_H, b_WqT_L, 256, 0,
        nullptr, b_qkvH, b_qkvL, 768, NTOK, 768, 256, nullptr, nullptr, nullptr, 0, 768);

    make_wfab<<<256, 256>>>(Wf, Wa, Wb);
    make_bias2<<<1, 256>>>(bf, Wa, ba, Wb, bb);
    sa_kernel<<<MCLUS, 256>>>();
    make_vcab<<<256, 64>>>(Wa, Wb);

    // cap: S = qp @ kc^T with FUSED row softmax -> P planes (no Scap, no rowsoft)
    bf16gemm<2,2><<<dim3(1, 512), 256, SM>>>(b_qkvH + (size_t)MCLUS * 768, b_qkvL + (size_t)MCLUS * 768, 768, 0,
        b_qkvH + 256, b_qkvL + 256, 768, 0, nullptr, b_PH, b_PL, 64,
        NPATH, 64, 256, nullptr, nullptr, nullptr, 0, MCLUS);

    // cac: S2 = kp @ qc^T (2-prod), col softmax, occ = E^T @ vp / l
    bf16gemm<2,0><<<dim3(1, 512), 256, SM>>>(b_qkvH + (size_t)MCLUS * 768 + 256, b_qkvL + (size_t)MCLUS * 768 + 256, 768, 0,
        b_qkvH, b_qkvL, 768, 0, p_Scac, nullptr, nullptr, 64,
        NPATH, 64, 256, nullptr, nullptr, nullptr, 0, MCLUS);
    colmax_part<<<64, 256>>>();
    cac_exp<<<64, 256>>>();
    bf16gemm<3,0><<<dim3(2, 1, 32), 256, SM>>>(b_EH, b_EL, 64, 1, vpH, vpL, 768, 1,
        p_occ, nullptr, nullptr, 256, MCLUS, 256, 2048, nullptr, nullptr, nullptr, 1, 256);
    cac_div<<<MCLUS, 256>>>();

    // linear attention
    linprep_kernel<<<NPATH, 256>>>(scl);
    klsum_kernel<<<256, 256>>>();
    zfac_kernel<<<NPATH / 8, 256>>>();
    bf16gemm<3,0><<<dim3(2, 2, 32), 256, SM>>>(b_klH, b_klL, 256, 1, vpH, vpL, 768, 1,
        p_kv, nullptr, nullptr, 256, 256, 256, 2048, nullptr, nullptr, nullptr, 1, 256);
    transpose_cvt<<<dim3(8, 8), dim3(32, 8)>>>(p_kv, 256, 256, 256, 256, b_kvT_H, b_kvT_L, 1, 0);

    conv_kernel<<<2048, 256>>>(dwcw, dwcb);
    // spin = zfac * (ql @ kv) + fm  (planes only)
    bf16gemm<3,0><<<dim3(2, 512), 256, SM>>>(b_qlH, b_qlL, 256, 0, b_kvT_H, b_kvT_L, 256, 0,
        nullptr, b_spinH, b_spinL, 256, NPATH, 256, 256, nullptr, p_zfac, p_spin, 0, 256);

    // small gated scorers (merged)
    gated_pair<<<8, 256>>>(Wa, ba, Wb, bb, Wc);

    // fused gated cross/self
    bf16gemm<2,1><<<dim3(4, 512), 256, SM>>>(b_PH, b_PL, 64, 0, b_vcabT_H, b_vcabT_L, 64, 0,
        p_Acp, nullptr, nullptr, 0, NPATH, 512, 64, ba, bb, Wc, 0, 512);
    bf16gemm<2,1><<<dim3(4, 512), 256, SM>>>(b_spinH, b_spinL, 256, 0, b_WfabT_H, b_WfabT_L, 256, 0,
        p_Asp, nullptr, nullptr, 0, NPATH, 512, 256, p_bfa2, p_bfb2, Wc, 0, 512);

    // fusion pooling
    fmax_small2<<<2, 256>>>();
    fmax_part2<<<dim3(256, 2), 256>>>();
    fmax_comb2<<<2, 256>>>();
    wsum_small2<<<2, 256>>>();
    wsum_planes<<<256, 256>>>(p_Acp, b_PH, b_PL, NPATH, 1, 256, 64, p_fw);
    wsum_planes<<<256, 256>>>(p_Asp, b_spinH, b_spinL, NPATH, 3, 256, 256, p_ft);
    post_both<<<2, 256>>>(Wf, bf);

    fuse_final<<<2, 256>>>(W1, b1, W2, b2, W3a, b3a, W3b, b3b, out);
}